// round 6
// baseline (speedup 1.0000x reference)
#include <cuda_runtime.h>

// CrossScaleAttention — fp32 baseline pipeline (resubmit; prior round was an
// infra container failure, not a kernel verdict).
// Stages: conv1x1+prelu (x3) -> im2col (x2) -> patch-norm -> GEMM1 (logits)
//         -> row softmax(x10) -> GEMM2 (attn apply) -> parity gather (stride-2 deconv).

#define BB   4
#define CCH  64           // C
#define CRR  32           // C/r
#define HH   96
#define WWD  96
#define HWP  (HH*WWD)     // 9216 pixels
#define HSS  48
#define LLN  (HSS*HSS)    // 2304 patches
#define KK1  (CRR*9)      // 288
#define NN2  (CCH*9)      // 576
#define HO   191

// ---- static scratch (no allocations allowed; __device__ globals are the
//      sanctioned mechanism) ----
__device__ float g_match[BB*CRR*HWP];            //  4.7 MB
__device__ float g_ref  [BB*CRR*LLN];            //  1.2 MB
__device__ float g_embed[BB*CCH*LLN];            //  2.4 MB
__device__ float g_Xim  [BB*HWP*KK1];            // 42.5 MB  [b][p][c*9+t]
__device__ float g_Wn   [BB*LLN*KK1];            // 10.6 MB  normalized ref patches
__device__ float g_Rim  [BB*LLN*NN2];            // 21.2 MB  embed patches [b][l][c*9+t]
__device__ float g_S    [(size_t)BB*HWP*LLN];    // 340 MB   logits -> softmax
__device__ float g_P2   [(size_t)BB*HWP*NN2];    // 85 MB    per-pixel mixed filters

// ---------------- conv1x1 + PReLU ----------------
// x: [B, 64, npix] -> out: [B, COUT, npix]
template<int COUT, int DST>
__global__ void __launch_bounds__(256) conv1x1k(
        const float* __restrict__ x, const float* __restrict__ wm,
        const float* __restrict__ bias, const float* __restrict__ aptr,
        int npix) {
    float* outg = (DST == 0) ? g_match : (DST == 1) ? g_embed : g_ref;
    __shared__ float ws[COUT*CCH];
    __shared__ float bs[COUT];
    int t = threadIdx.x;
    for (int i = t; i < COUT*CCH; i += blockDim.x) ws[i] = wm[i];
    if (t < COUT) bs[t] = bias[t];
    __syncthreads();
    float a = aptr[0];
    int b = blockIdx.y;
    int p = blockIdx.x * blockDim.x + t;
    if (p >= npix) return;
    const float* xb = x + (size_t)b * CCH * npix;
    float acc[COUT];
    #pragma unroll
    for (int o = 0; o < COUT; o++) acc[o] = bs[o];
    #pragma unroll
    for (int c = 0; c < CCH; c++) {
        float xv = xb[(size_t)c*npix + p];
        #pragma unroll
        for (int o = 0; o < COUT; o++) acc[o] = fmaf(xv, ws[o*CCH + c], acc[o]);
    }
    float* ob = outg + (size_t)b * COUT * npix;
    #pragma unroll
    for (int o = 0; o < COUT; o++) {
        float v = acc[o];
        ob[(size_t)o*npix + p] = (v >= 0.f) ? v : a * v;
    }
}

// ---------------- im2col 3x3 (same pad) ----------------
// MODE 0: g_match [B,32,96,96] -> g_Xim [b][p][c*9+t]
// MODE 1: g_embed [B,64,48,48] -> g_Rim [b][l][c*9+t]
template<int MODE>
__global__ void im2col3k() {
    const float* src = (MODE == 0) ? g_match : g_embed;
    float*       dst = (MODE == 0) ? g_Xim  : g_Rim;
    const int Cn = (MODE == 0) ? CRR : CCH;
    const int Ht = (MODE == 0) ? HH  : HSS;
    const int Wt = (MODE == 0) ? WWD : HSS;
    int idx = blockIdx.x * blockDim.x + threadIdx.x;
    int total = BB * Cn * Ht * Wt;
    if (idx >= total) return;
    int xq = idx % Wt; int tmp = idx / Wt;
    int yq = tmp % Ht; tmp /= Ht;
    int c  = tmp % Cn; int b = tmp / Cn;
    const float* s = src + ((size_t)(b*Cn + c)) * Ht * Wt;
    float* d = dst + ((size_t)b*Ht*Wt + (size_t)yq*Wt + xq) * (Cn*9) + c*9;
    #pragma unroll
    for (int i = 0; i < 3; i++) {
        int yy = yq + i - 1;
        #pragma unroll
        for (int j = 0; j < 3; j++) {
            int xx = xq + j - 1;
            float v = (yy >= 0 && yy < Ht && xx >= 0 && xx < Wt) ? s[yy*Wt + xx] : 0.f;
            d[i*3 + j] = v;
        }
    }
}

// ---------------- ref patches, L2-normalized ----------------
// one warp per (b,l); lane = channel (Cr=32)
__global__ void ref_norm_kernel() {
    int warp = (blockIdx.x * blockDim.x + threadIdx.x) >> 5;
    int lane = threadIdx.x & 31;
    if (warp >= BB * LLN) return;
    int b = warp / LLN, l = warp % LLN;
    int ly = l / HSS, lx = l % HSS;
    const float* s = g_ref + ((size_t)(b*CRR + lane)) * LLN;
    float v[9]; float ss = 0.f;
    #pragma unroll
    for (int i = 0; i < 3; i++)
        #pragma unroll
        for (int j = 0; j < 3; j++) {
            int yy = ly + i - 1, xx = lx + j - 1;
            float vv = (yy >= 0 && yy < HSS && xx >= 0 && xx < HSS) ? s[yy*HSS + xx] : 0.f;
            v[i*3 + j] = vv; ss = fmaf(vv, vv, ss);
        }
    #pragma unroll
    for (int off = 16; off; off >>= 1) ss += __shfl_xor_sync(0xffffffffu, ss, off);
    float inv = 1.f / fmaxf(sqrtf(ss), 1e-4f);
    float* d = g_Wn + ((size_t)b*LLN + l) * KK1 + lane*9;
    #pragma unroll
    for (int t = 0; t < 9; t++) d[t] = v[t] * inv;
}

// ---------------- GEMM1: logits = Xim [M,K] * Wn[N,K]^T ----------------
// M=9216, N=2304, K=288 — all tile-exact. 128x128x8, 8x8 per thread.
__global__ void __launch_bounds__(256) gemm1_kernel() {
    const int M = HWP, N = LLN, K = KK1;
    int bz = blockIdx.z;
    const float* __restrict__ A  = g_Xim + (size_t)bz*M*K;
    const float* __restrict__ Bp = g_Wn  + (size_t)bz*N*K;
    float* __restrict__ Cp = g_S + (size_t)bz*M*N;
    __shared__ float As[8][132];
    __shared__ float Bs[8][132];
    int t = threadIdx.x;
    int m0 = blockIdx.y * 128, n0 = blockIdx.x * 128;
    int lr = t >> 1, lc = (t & 1) * 4;
    int tx = t & 15, ty = t >> 4;
    float acc[8][8];
    #pragma unroll
    for (int i = 0; i < 8; i++)
        #pragma unroll
        for (int j = 0; j < 8; j++) acc[i][j] = 0.f;

    const float* aptr = A  + (size_t)(m0+lr)*K + lc;
    const float* bptr = Bp + (size_t)(n0+lr)*K + lc;
    float4 av = *(const float4*)(aptr);
    float4 bv = *(const float4*)(bptr);
    for (int k0 = 0; k0 < K; k0 += 8) {
        As[lc+0][lr]=av.x; As[lc+1][lr]=av.y; As[lc+2][lr]=av.z; As[lc+3][lr]=av.w;
        Bs[lc+0][lr]=bv.x; Bs[lc+1][lr]=bv.y; Bs[lc+2][lr]=bv.z; Bs[lc+3][lr]=bv.w;
        __syncthreads();
        if (k0 + 8 < K) {
            av = *(const float4*)(aptr + k0 + 8);
            bv = *(const float4*)(bptr + k0 + 8);
        }
        #pragma unroll
        for (int kk = 0; kk < 8; kk++) {
            float ar[8], br[8];
            #pragma unroll
            for (int i = 0; i < 8; i++) ar[i] = As[kk][ty*8 + i];
            #pragma unroll
            for (int j = 0; j < 8; j++) br[j] = Bs[kk][tx*8 + j];
            #pragma unroll
            for (int i = 0; i < 8; i++)
                #pragma unroll
                for (int j = 0; j < 8; j++) acc[i][j] = fmaf(ar[i], br[j], acc[i][j]);
        }
        __syncthreads();
    }
    #pragma unroll
    for (int i = 0; i < 8; i++) {
        float* cr = Cp + (size_t)(m0 + ty*8 + i)*N + n0 + tx*8;
        *(float4*)(cr)     = make_float4(acc[i][0], acc[i][1], acc[i][2], acc[i][3]);
        *(float4*)(cr + 4) = make_float4(acc[i][4], acc[i][5], acc[i][6], acc[i][7]);
    }
}

// ---------------- softmax over L per row (in place, with SCALE=10) ----------------
__global__ void __launch_bounds__(256) softmax_kernel() {
    float* r = g_S + (size_t)blockIdx.x * LLN;   // LLN = 9*256
    int t = threadIdx.x;
    float v[9]; float m = -1e30f;
    #pragma unroll
    for (int i = 0; i < 9; i++) { v[i] = r[i*256 + t]; m = fmaxf(m, v[i]); }
    __shared__ float red[256];
    red[t] = m; __syncthreads();
    #pragma unroll
    for (int s = 128; s > 0; s >>= 1) { if (t < s) red[t] = fmaxf(red[t], red[t+s]); __syncthreads(); }
    m = red[0];
    __syncthreads();
    float sum = 0.f;
    #pragma unroll
    for (int i = 0; i < 9; i++) { v[i] = __expf(10.f * (v[i] - m)); sum += v[i]; }
    red[t] = sum; __syncthreads();
    #pragma unroll
    for (int s = 128; s > 0; s >>= 1) { if (t < s) red[t] += red[t+s]; __syncthreads(); }
    float inv = 1.f / red[0];
    #pragma unroll
    for (int i = 0; i < 9; i++) r[i*256 + t] = v[i] * inv;
}

// ---------------- GEMM2: P2 = S [M,K] * Rim [K,N] ----------------
// M=9216, K=2304, N=576 (edge guard on N only).
__global__ void __launch_bounds__(256) gemm2_kernel() {
    const int M = HWP, N = NN2, K = LLN;
    int bz = blockIdx.z;
    const float* __restrict__ A  = g_S   + (size_t)bz*M*K;
    const float* __restrict__ Bp = g_Rim + (size_t)bz*K*N;
    float* __restrict__ Cp = g_P2 + (size_t)bz*M*N;
    __shared__ float As[8][132];
    __shared__ float Bs[8][132];
    int t = threadIdx.x;
    int m0 = blockIdx.y * 128, n0 = blockIdx.x * 128;
    int lr = t >> 1, lc = (t & 1) * 4;
    int brow = t >> 5, bcol = (t & 31) * 4;
    int tx = t & 15, ty = t >> 4;
    bool bok = (n0 + bcol < N);
    float acc[8][8];
    #pragma unroll
    for (int i = 0; i < 8; i++)
        #pragma unroll
        for (int j = 0; j < 8; j++) acc[i][j] = 0.f;

    const float* aptr = A + (size_t)(m0+lr)*K + lc;
    const float* bptr = Bp + (size_t)brow*N + n0 + bcol;
    float4 av = *(const float4*)(aptr);
    float4 bv = make_float4(0.f, 0.f, 0.f, 0.f);
    if (bok) bv = *(const float4*)(bptr);
    for (int k0 = 0; k0 < K; k0 += 8) {
        As[lc+0][lr]=av.x; As[lc+1][lr]=av.y; As[lc+2][lr]=av.z; As[lc+3][lr]=av.w;
        *(float4*)&Bs[brow][bcol] = bv;
        __syncthreads();
        if (k0 + 8 < K) {
            av = *(const float4*)(aptr + k0 + 8);
            if (bok) bv = *(const float4*)(bptr + (size_t)(k0 + 8)*N);
        }
        #pragma unroll
        for (int kk = 0; kk < 8; kk++) {
            float ar[8], br[8];
            #pragma unroll
            for (int i = 0; i < 8; i++) ar[i] = As[kk][ty*8 + i];
            #pragma unroll
            for (int j = 0; j < 8; j++) br[j] = Bs[kk][tx*8 + j];
            #pragma unroll
            for (int i = 0; i < 8; i++)
                #pragma unroll
                for (int j = 0; j < 8; j++) acc[i][j] = fmaf(ar[i], br[j], acc[i][j]);
        }
        __syncthreads();
    }
    int col = n0 + tx*8;
    if (col < N) {
        #pragma unroll
        for (int i = 0; i < 8; i++) {
            float* cr = Cp + (size_t)(m0 + ty*8 + i)*N + col;
            *(float4*)(cr)     = make_float4(acc[i][0], acc[i][1], acc[i][2], acc[i][3]);
            *(float4*)(cr + 4) = make_float4(acc[i][4], acc[i][5], acc[i][6], acc[i][7]);
        }
    }
}

// ---------------- stride-2 transpose-conv gather ----------------
// out[b,c,Y,X] = (1/6) * sum over parity-selected (y,kh),(x,kw) of
//               P2[b][y*96+x][c*9+kh*3+kw]
__global__ void gather_kernel(float* __restrict__ out) {
    long idx = (long)blockIdx.x * blockDim.x + threadIdx.x;
    const long total = (long)BB * CCH * HO * HO;
    if (idx >= total) return;
    int X = (int)(idx % HO); long tmp = idx / HO;
    int Y = (int)(tmp % HO); tmp /= HO;
    int c = (int)(tmp % CCH); int b = (int)(tmp / CCH);
    const float* __restrict__ Pb = g_P2 + (size_t)b * HWP * NN2 + c*9;

    float s;
    if ((Y & 1) == 0 && (X & 1) == 0) {
        int p = (Y >> 1)*WWD + (X >> 1);
        s = Pb[(size_t)p*NN2 + 4];                       // kh=1,kw=1
    } else if ((Y & 1) == 0) {
        int p0 = (Y >> 1)*WWD + ((X-1) >> 1);
        int p1 = (Y >> 1)*WWD + ((X+1) >> 1);
        s = Pb[(size_t)p0*NN2 + 5] + Pb[(size_t)p1*NN2 + 3];   // kw=2 / kw=0
    } else if ((X & 1) == 0) {
        int p0 = ((Y-1) >> 1)*WWD + (X >> 1);
        int p1 = ((Y+1) >> 1)*WWD + (X >> 1);
        s = Pb[(size_t)p0*NN2 + 7] + Pb[(size_t)p1*NN2 + 1];   // kh=2 / kh=0
    } else {
        int ya = (Y-1) >> 1, yb = (Y+1) >> 1;
        int xa = (X-1) >> 1, xb = (X+1) >> 1;
        s = Pb[(size_t)(ya*WWD + xa)*NN2 + 8]                  // kh=2,kw=2
          + Pb[(size_t)(ya*WWD + xb)*NN2 + 6]                  // kh=2,kw=0
          + Pb[(size_t)(yb*WWD + xa)*NN2 + 2]                  // kh=0,kw=2
          + Pb[(size_t)(yb*WWD + xb)*NN2 + 0];                 // kh=0,kw=0
    }
    out[idx] = s * (1.f/6.f);
}

// ---------------- launch ----------------
extern "C" void kernel_launch(void* const* d_in, const int* in_sizes, int n_in,
                              void* d_out, int out_size) {
    const float* input = (const float*)d_in[0];
    const float* small = (const float*)d_in[1];
    const float* w1    = (const float*)d_in[2];
    const float* b1    = (const float*)d_in[3];
    const float* a1    = (const float*)d_in[4];
    const float* w2    = (const float*)d_in[5];
    const float* b2    = (const float*)d_in[6];
    const float* a2    = (const float*)d_in[7];
    const float* wa    = (const float*)d_in[8];
    const float* ba    = (const float*)d_in[9];
    const float* aa    = (const float*)d_in[10];
    float* out = (float*)d_out;

    conv1x1k<CRR, 0><<<dim3(HWP/256, BB), 256>>>(input, w1, b1, a1, HWP);
    conv1x1k<CCH, 1><<<dim3(LLN/256, BB), 256>>>(small, wa, ba, aa, LLN);
    conv1x1k<CRR, 2><<<dim3(LLN/256, BB), 256>>>(small, w2, b2, a2, LLN);

    im2col3k<0><<<(BB*CRR*HWP + 255)/256, 256>>>();
    im2col3k<1><<<(BB*CCH*LLN + 255)/256, 256>>>();
    ref_norm_kernel<<<(BB*LLN*32 + 255)/256, 256>>>();

    gemm1_kernel<<<dim3(LLN/128, HWP/128, BB), 256>>>();
    softmax_kernel<<<BB*HWP, 256>>>();
    gemm2_kernel<<<dim3((NN2 + 127)/128, HWP/128, BB), 256>>>();

    gather_kernel<<<(int)(((long)BB*CCH*HO*HO + 255)/256), 256>>>(out);
}

// round 7
// speedup vs baseline: 1.2742x; 1.2742x over previous
#include <cuda_runtime.h>

// CrossScaleAttention — round 7.
// Changes vs R6 (3996us):
//  * GEMM1 (49 GF, K=288) replaced by Gram GEMM D = match x ref^T (K=32, 5.4 GF)
//    + diagonal 9-tap stencil fused into the softmax kernel (patch dot-products
//    decompose over shifts). Norm becomes a 9-tap stencil on n2[l]=sum_c ref^2.
//  * GEMM2 inner loop uses packed fma.rn.f32x2 (Blackwell FFMA2, 2x fp32 issue).

#define BB   4
#define CCH  64           // C
#define CRR  32           // C/r
#define HH   96
#define WWD  96
#define HWP  (HH*WWD)     // 9216 pixels
#define HSS  48
#define LLN  (HSS*HSS)    // 2304 patches
#define NN2  (CCH*9)      // 576
#define HO   191

// ---- static scratch (no allocations allowed) ----
__device__ float g_match[BB*HWP*CRR];            //  4.7 MB  [b][p][c]
__device__ float g_ref  [BB*LLN*CRR];            //  1.2 MB  [b][l][c]
__device__ float g_embed[BB*CCH*LLN];            //  2.4 MB  [b][c][l]
__device__ float g_Rim  [BB*LLN*NN2];            // 21.2 MB  embed patches [b][l][c*9+t]
__device__ float g_D    [(size_t)BB*HWP*LLN];    // 340 MB   channel Gram matrix
__device__ float g_S    [(size_t)BB*HWP*LLN];    // 340 MB   softmax probs
__device__ float g_P2   [(size_t)BB*HWP*NN2];    // 85 MB    per-pixel mixed filters
__device__ float g_n2   [BB*LLN];
__device__ float g_invn [BB*LLN];

// ---- packed fp32x2 helpers (Blackwell FFMA2 path) ----
__device__ __forceinline__ unsigned long long dup2(float x) {
    unsigned long long r;
    asm("mov.b64 %0, {%1, %1};" : "=l"(r) : "f"(x));
    return r;
}
__device__ __forceinline__ unsigned long long pk2(float x, float y) {
    unsigned long long r;
    asm("mov.b64 %0, {%1, %2};" : "=l"(r) : "f"(x), "f"(y));
    return r;
}
__device__ __forceinline__ void ffma2(unsigned long long& d,
                                      unsigned long long a, unsigned long long b) {
    asm("fma.rn.f32x2 %0, %1, %2, %0;" : "+l"(d) : "l"(a), "l"(b));
}

// ---------------- conv1x1 + PReLU ----------------
// x: [B, 64, npix] -> DST 0: g_match [b][p][32] ; DST 1: g_embed [b][64][l] ;
//                     DST 2: g_ref   [b][l][32]
template<int COUT, int DST>
__global__ void __launch_bounds__(256) conv1x1k(
        const float* __restrict__ x, const float* __restrict__ wm,
        const float* __restrict__ bias, const float* __restrict__ aptr,
        int npix) {
    float* outg = (DST == 0) ? g_match : (DST == 1) ? g_embed : g_ref;
    __shared__ float ws[COUT*CCH];
    __shared__ float bs[COUT];
    int t = threadIdx.x;
    for (int i = t; i < COUT*CCH; i += blockDim.x) ws[i] = wm[i];
    if (t < COUT) bs[t] = bias[t];
    __syncthreads();
    float a = aptr[0];
    int b = blockIdx.y;
    int p = blockIdx.x * blockDim.x + t;
    if (p >= npix) return;
    const float* xb = x + (size_t)b * CCH * npix;
    float acc[COUT];
    #pragma unroll
    for (int o = 0; o < COUT; o++) acc[o] = bs[o];
    #pragma unroll
    for (int c = 0; c < CCH; c++) {
        float xv = xb[(size_t)c*npix + p];
        #pragma unroll
        for (int o = 0; o < COUT; o++) acc[o] = fmaf(xv, ws[o*CCH + c], acc[o]);
    }
    if (DST == 1) {           // channel-major
        float* ob = outg + (size_t)b * COUT * npix;
        #pragma unroll
        for (int o = 0; o < COUT; o++) {
            float v = acc[o];
            ob[(size_t)o*npix + p] = (v >= 0.f) ? v : a * v;
        }
    } else {                  // pixel-major [p][COUT]
        float* ob = outg + ((size_t)b * npix + p) * COUT;
        #pragma unroll
        for (int o = 0; o < COUT; o += 4) {
            float4 vv;
            vv.x = (acc[o+0] >= 0.f) ? acc[o+0] : a * acc[o+0];
            vv.y = (acc[o+1] >= 0.f) ? acc[o+1] : a * acc[o+1];
            vv.z = (acc[o+2] >= 0.f) ? acc[o+2] : a * acc[o+2];
            vv.w = (acc[o+3] >= 0.f) ? acc[o+3] : a * acc[o+3];
            *(float4*)(ob + o) = vv;
        }
    }
}

// ---------------- im2col 3x3 (same pad) for embed -> Rim ----------------
__global__ void im2col3k() {
    const int Cn = CCH, Ht = HSS, Wt = HSS;
    int idx = blockIdx.x * blockDim.x + threadIdx.x;
    int total = BB * Cn * Ht * Wt;
    if (idx >= total) return;
    int xq = idx % Wt; int tmp = idx / Wt;
    int yq = tmp % Ht; tmp /= Ht;
    int c  = tmp % Cn; int b = tmp / Cn;
    const float* s = g_embed + ((size_t)(b*Cn + c)) * Ht * Wt;
    float* d = g_Rim + ((size_t)b*Ht*Wt + (size_t)yq*Wt + xq) * (Cn*9) + c*9;
    #pragma unroll
    for (int i = 0; i < 3; i++) {
        int yy = yq + i - 1;
        #pragma unroll
        for (int j = 0; j < 3; j++) {
            int xx = xq + j - 1;
            float v = (yy >= 0 && yy < Ht && xx >= 0 && xx < Wt) ? s[yy*Wt + xx] : 0.f;
            d[i*3 + j] = v;
        }
    }
}

// ---------------- per-pixel channel energy + patch inv-norm ----------------
__global__ void n2_kernel() {
    int idx = blockIdx.x * blockDim.x + threadIdx.x;
    if (idx >= BB*LLN) return;
    const float* r = g_ref + (size_t)idx * CRR;
    float s = 0.f;
    #pragma unroll
    for (int c = 0; c < CRR; c += 4) {
        float4 v = *(const float4*)(r + c);
        s = fmaf(v.x, v.x, s); s = fmaf(v.y, v.y, s);
        s = fmaf(v.z, v.z, s); s = fmaf(v.w, v.w, s);
    }
    g_n2[idx] = s;
}

__global__ void invn_kernel() {
    int idx = blockIdx.x * blockDim.x + threadIdx.x;
    if (idx >= BB*LLN) return;
    int b = idx / LLN, l = idx % LLN;
    int ly = l / HSS, lx = l % HSS;
    const float* n2b = g_n2 + b*LLN;
    float s = 0.f;
    #pragma unroll
    for (int dy = -1; dy <= 1; dy++)
        #pragma unroll
        for (int dx = -1; dx <= 1; dx++) {
            int yy = ly + dy, xx = lx + dx;
            if (yy >= 0 && yy < HSS && xx >= 0 && xx < HSS)
                s += n2b[yy*HSS + xx];
        }
    g_invn[idx] = 1.f / fmaxf(sqrtf(s), 1e-4f);
}

// ---------------- Gram GEMM: D = match [M,32] * ref [N,32]^T ----------------
// M=9216, N=2304, K=32. 128x128 tile, 8x8 per thread.
__global__ void __launch_bounds__(256) gemmD_kernel() {
    const int M = HWP, N = LLN, K = CRR;
    int bz = blockIdx.z;
    const float* __restrict__ A  = g_match + (size_t)bz*M*K;
    const float* __restrict__ Bp = g_ref   + (size_t)bz*N*K;
    float* __restrict__ Dp = g_D + (size_t)bz*M*N;
    __shared__ float As[32][132];
    __shared__ float Bs[32][132];
    int t = threadIdx.x;
    int m0 = blockIdx.y * 128, n0 = blockIdx.x * 128;
    int lr = t >> 1, lc = (t & 1) * 16;
    int tx = t & 15, ty = t >> 4;
    #pragma unroll
    for (int q = 0; q < 4; q++) {
        float4 av = *(const float4*)(A  + (size_t)(m0+lr)*K + lc + q*4);
        As[lc+q*4+0][lr]=av.x; As[lc+q*4+1][lr]=av.y;
        As[lc+q*4+2][lr]=av.z; As[lc+q*4+3][lr]=av.w;
        float4 bv = *(const float4*)(Bp + (size_t)(n0+lr)*K + lc + q*4);
        Bs[lc+q*4+0][lr]=bv.x; Bs[lc+q*4+1][lr]=bv.y;
        Bs[lc+q*4+2][lr]=bv.z; Bs[lc+q*4+3][lr]=bv.w;
    }
    __syncthreads();
    float acc[8][8];
    #pragma unroll
    for (int i = 0; i < 8; i++)
        #pragma unroll
        for (int j = 0; j < 8; j++) acc[i][j] = 0.f;
    #pragma unroll 4
    for (int kk = 0; kk < 32; kk++) {
        float ar[8], br[8];
        #pragma unroll
        for (int i = 0; i < 8; i++) ar[i] = As[kk][ty*8 + i];
        #pragma unroll
        for (int j = 0; j < 8; j++) br[j] = Bs[kk][tx*8 + j];
        #pragma unroll
        for (int i = 0; i < 8; i++)
            #pragma unroll
            for (int j = 0; j < 8; j++) acc[i][j] = fmaf(ar[i], br[j], acc[i][j]);
    }
    #pragma unroll
    for (int i = 0; i < 8; i++) {
        float* dr = Dp + (size_t)(m0 + ty*8 + i)*N + n0 + tx*8;
        *(float4*)(dr)     = make_float4(acc[i][0], acc[i][1], acc[i][2], acc[i][3]);
        *(float4*)(dr + 4) = make_float4(acc[i][4], acc[i][5], acc[i][6], acc[i][7]);
    }
}

// ---------------- fused diagonal stencil + softmax ----------------
// logit[p,l] = invn[l] * sum_{d in 3x3} D[p+d, l+d]  (both-valid taps only),
// then softmax over l with SCALE=10, written to g_S.
__global__ void __launch_bounds__(256) logits_softmax_kernel() {
    int row = blockIdx.x;
    int b = row / HWP, p = row % HWP;
    int py = p / WWD, px = p % WWD;
    const float* __restrict__ Db = g_D + (size_t)b*HWP*LLN;
    const float* __restrict__ invn = g_invn + b*LLN;
    float* __restrict__ Sr = g_S + (size_t)row * LLN;

    const float* rp[9]; bool rv[9]; int co[9];
    #pragma unroll
    for (int dy = -1; dy <= 1; dy++)
        #pragma unroll
        for (int dx = -1; dx <= 1; dx++) {
            int k = (dy+1)*3 + (dx+1);
            int yy = py + dy, xx = px + dx;
            rv[k] = (yy >= 0 && yy < HH && xx >= 0 && xx < WWD);
            rp[k] = Db + (size_t)(yy*WWD + xx) * LLN;
            co[k] = dy*HSS + dx;
        }

    int t = threadIdx.x;
    float v[9]; float m = -1e30f;
    #pragma unroll
    for (int i = 0; i < 9; i++) {
        int l = i*256 + t;
        int ly = l / HSS, lx = l % HSS;
        float s = 0.f;
        #pragma unroll
        for (int dy = -1; dy <= 1; dy++)
            #pragma unroll
            for (int dx = -1; dx <= 1; dx++) {
                int k = (dy+1)*3 + (dx+1);
                int yy = ly + dy, xx = lx + dx;
                bool ok = rv[k] && (yy >= 0) && (yy < HSS) && (xx >= 0) && (xx < HSS);
                if (ok) s += rp[k][l + co[k]];
            }
        v[i] = 10.f * s * invn[l];
        m = fmaxf(m, v[i]);
    }
    __shared__ float red[256];
    red[t] = m; __syncthreads();
    #pragma unroll
    for (int s = 128; s > 0; s >>= 1) { if (t < s) red[t] = fmaxf(red[t], red[t+s]); __syncthreads(); }
    m = red[0];
    __syncthreads();
    float sum = 0.f;
    #pragma unroll
    for (int i = 0; i < 9; i++) { v[i] = __expf(v[i] - m); sum += v[i]; }
    red[t] = sum; __syncthreads();
    #pragma unroll
    for (int s = 128; s > 0; s >>= 1) { if (t < s) red[t] += red[t+s]; __syncthreads(); }
    float inv = 1.f / red[0];
    #pragma unroll
    for (int i = 0; i < 9; i++) Sr[i*256 + t] = v[i] * inv;
}

// ---------------- GEMM2: P2 = S [M,K] * Rim [K,N], packed f32x2 ----------------
// M=9216, K=2304, N=576 (edge guard on N only).
__global__ void __launch_bounds__(256) gemm2_kernel() {
    const int M = HWP, N = NN2, K = LLN;
    int bz = blockIdx.z;
    const float* __restrict__ A  = g_S   + (size_t)bz*M*K;
    const float* __restrict__ Bp = g_Rim + (size_t)bz*K*N;
    float* __restrict__ Cp = g_P2 + (size_t)bz*M*N;
    __shared__ float As[8][132];
    __shared__ float Bs[8][132];
    int t = threadIdx.x;
    int m0 = blockIdx.y * 128, n0 = blockIdx.x * 128;
    int lr = t >> 1, lc = (t & 1) * 4;
    int brow = t >> 5, bcol = (t & 31) * 4;
    int tx = t & 15, ty = t >> 4;
    bool bok = (n0 + bcol < N);
    unsigned long long acc2[8][4];
    #pragma unroll
    for (int i = 0; i < 8; i++)
        #pragma unroll
        for (int j = 0; j < 4; j++) acc2[i][j] = 0ULL;

    const float* aptr = A + (size_t)(m0+lr)*K + lc;
    const float* bptr = Bp + (size_t)brow*N + n0 + bcol;
    float4 av = *(const float4*)(aptr);
    float4 bv = make_float4(0.f, 0.f, 0.f, 0.f);
    if (bok) bv = *(const float4*)(bptr);
    for (int k0 = 0; k0 < K; k0 += 8) {
        As[lc+0][lr]=av.x; As[lc+1][lr]=av.y; As[lc+2][lr]=av.z; As[lc+3][lr]=av.w;
        *(float4*)&Bs[brow][bcol] = bv;
        __syncthreads();
        if (k0 + 8 < K) {
            av = *(const float4*)(aptr + k0 + 8);
            if (bok) bv = *(const float4*)(bptr + (size_t)(k0 + 8)*N);
        }
        #pragma unroll
        for (int kk = 0; kk < 8; kk++) {
            float4 aq0 = *(const float4*)&As[kk][ty*8];
            float4 aq1 = *(const float4*)&As[kk][ty*8 + 4];
            float4 bq0 = *(const float4*)&Bs[kk][tx*8];
            float4 bq1 = *(const float4*)&Bs[kk][tx*8 + 4];
            unsigned long long a2[8];
            a2[0]=dup2(aq0.x); a2[1]=dup2(aq0.y); a2[2]=dup2(aq0.z); a2[3]=dup2(aq0.w);
            a2[4]=dup2(aq1.x); a2[5]=dup2(aq1.y); a2[6]=dup2(aq1.z); a2[7]=dup2(aq1.w);
            unsigned long long b2[4];
            b2[0]=pk2(bq0.x,bq0.y); b2[1]=pk2(bq0.z,bq0.w);
            b2[2]=pk2(bq1.x,bq1.y); b2[3]=pk2(bq1.z,bq1.w);
            #pragma unroll
            for (int i = 0; i < 8; i++)
                #pragma unroll
                for (int j = 0; j < 4; j++) ffma2(acc2[i][j], a2[i], b2[j]);
        }
        __syncthreads();
    }
    int col = n0 + tx*8;
    if (col < N) {
        #pragma unroll
        for (int i = 0; i < 8; i++) {
            float2 f0 = *reinterpret_cast<float2*>(&acc2[i][0]);
            float2 f1 = *reinterpret_cast<float2*>(&acc2[i][1]);
            float2 f2 = *reinterpret_cast<float2*>(&acc2[i][2]);
            float2 f3 = *reinterpret_cast<float2*>(&acc2[i][3]);
            float* cr = Cp + (size_t)(m0 + ty*8 + i)*N + col;
            *(float4*)(cr)     = make_float4(f0.x, f0.y, f1.x, f1.y);
            *(float4*)(cr + 4) = make_float4(f2.x, f2.y, f3.x, f3.y);
        }
    }
}

// ---------------- stride-2 transpose-conv gather ----------------
__global__ void gather_kernel(float* __restrict__ out) {
    long idx = (long)blockIdx.x * blockDim.x + threadIdx.x;
    const long total = (long)BB * CCH * HO * HO;
    if (idx >= total) return;
    int X = (int)(idx % HO); long tmp = idx / HO;
    int Y = (int)(tmp % HO); tmp /= HO;
    int c = (int)(tmp % CCH); int b = (int)(tmp / CCH);
    const float* __restrict__ Pb = g_P2 + (size_t)b * HWP * NN2 + c*9;

    float s;
    if ((Y & 1) == 0 && (X & 1) == 0) {
        int p = (Y >> 1)*WWD + (X >> 1);
        s = Pb[(size_t)p*NN2 + 4];                       // kh=1,kw=1
    } else if ((Y & 1) == 0) {
        int p0 = (Y >> 1)*WWD + ((X-1) >> 1);
        int p1 = (Y >> 1)*WWD + ((X+1) >> 1);
        s = Pb[(size_t)p0*NN2 + 5] + Pb[(size_t)p1*NN2 + 3];   // kw=2 / kw=0
    } else if ((X & 1) == 0) {
        int p0 = ((Y-1) >> 1)*WWD + (X >> 1);
        int p1 = ((Y+1) >> 1)*WWD + (X >> 1);
        s = Pb[(size_t)p0*NN2 + 7] + Pb[(size_t)p1*NN2 + 1];   // kh=2 / kh=0
    } else {
        int ya = (Y-1) >> 1, yb = (Y+1) >> 1;
        int xa = (X-1) >> 1, xb = (X+1) >> 1;
        s = Pb[(size_t)(ya*WWD + xa)*NN2 + 8]
          + Pb[(size_t)(ya*WWD + xb)*NN2 + 6]
          + Pb[(size_t)(yb*WWD + xa)*NN2 + 2]
          + Pb[(size_t)(yb*WWD + xb)*NN2 + 0];
    }
    out[idx] = s * (1.f/6.f);
}

// ---------------- launch ----------------
extern "C" void kernel_launch(void* const* d_in, const int* in_sizes, int n_in,
                              void* d_out, int out_size) {
    const float* input = (const float*)d_in[0];
    const float* small = (const float*)d_in[1];
    const float* w1    = (const float*)d_in[2];
    const float* b1    = (const float*)d_in[3];
    const float* a1    = (const float*)d_in[4];
    const float* w2    = (const float*)d_in[5];
    const float* b2    = (const float*)d_in[6];
    const float* a2    = (const float*)d_in[7];
    const float* wa    = (const float*)d_in[8];
    const float* ba    = (const float*)d_in[9];
    const float* aa    = (const float*)d_in[10];
    float* out = (float*)d_out;

    conv1x1k<CRR, 0><<<dim3(HWP/256, BB), 256>>>(input, w1, b1, a1, HWP);
    conv1x1k<CCH, 1><<<dim3(LLN/256, BB), 256>>>(small, wa, ba, aa, LLN);
    conv1x1k<CRR, 2><<<dim3(LLN/256, BB), 256>>>(small, w2, b2, a2, LLN);

    im2col3k<<<(BB*CCH*LLN + 255)/256, 256>>>();
    n2_kernel<<<(BB*LLN + 255)/256, 256>>>();
    invn_kernel<<<(BB*LLN + 255)/256, 256>>>();

    gemmD_kernel<<<dim3(LLN/128, HWP/128, BB), 256>>>();
    logits_softmax_kernel<<<BB*HWP, 256>>>();
    gemm2_kernel<<<dim3((NN2 + 127)/128, HWP/128, BB), 256>>>();

    gather_kernel<<<(int)(((long)BB*CCH*HO*HO + 255)/256), 256>>>(out);
}

// round 8
// speedup vs baseline: 1.5420x; 1.2101x over previous
#include <cuda_runtime.h>

// CrossScaleAttention — round 8.
// Changes vs R7 (3136us):
//  * GEMM2 rewritten with warp-level tensor-core mma.sync.m16n8k8.tf32
//    (FFMA2 was measured-neutral; GEMM2 was ~2.2ms on the scalar FMA pipe).
//    tf32 only on this GEMM; logits/softmax path stays full fp32.

#define BB   4
#define CCH  64           // C
#define CRR  32           // C/r
#define HH   96
#define WWD  96
#define HWP  (HH*WWD)     // 9216 pixels
#define HSS  48
#define LLN  (HSS*HSS)    // 2304 patches
#define NN2  (CCH*9)      // 576
#define HO   191

// ---- static scratch (no allocations allowed) ----
__device__ float g_match[BB*HWP*CRR];            //  4.7 MB  [b][p][c]
__device__ float g_ref  [BB*LLN*CRR];            //  1.2 MB  [b][l][c]
__device__ float g_embed[BB*CCH*LLN];            //  2.4 MB  [b][c][l]
__device__ float g_Rim  [BB*LLN*NN2];            // 21.2 MB  embed patches [b][l][c*9+t]
__device__ float g_D    [(size_t)BB*HWP*LLN];    // 340 MB   channel Gram matrix
__device__ float g_S    [(size_t)BB*HWP*LLN];    // 340 MB   softmax probs
__device__ float g_P2   [(size_t)BB*HWP*NN2];    // 85 MB    per-pixel mixed filters
__device__ float g_n2   [BB*LLN];
__device__ float g_invn [BB*LLN];

// ---- tf32 helper ----
__device__ __forceinline__ unsigned to_tf32(float x) {
    unsigned r;
    asm("cvt.rna.tf32.f32 %0, %1;" : "=r"(r) : "f"(x));
    return r;
}

// ---------------- conv1x1 + PReLU ----------------
// x: [B, 64, npix] -> DST 0: g_match [b][p][32] ; DST 1: g_embed [b][64][l] ;
//                     DST 2: g_ref   [b][l][32]
template<int COUT, int DST>
__global__ void __launch_bounds__(256) conv1x1k(
        const float* __restrict__ x, const float* __restrict__ wm,
        const float* __restrict__ bias, const float* __restrict__ aptr,
        int npix) {
    float* outg = (DST == 0) ? g_match : (DST == 1) ? g_embed : g_ref;
    __shared__ float ws[COUT*CCH];
    __shared__ float bs[COUT];
    int t = threadIdx.x;
    for (int i = t; i < COUT*CCH; i += blockDim.x) ws[i] = wm[i];
    if (t < COUT) bs[t] = bias[t];
    __syncthreads();
    float a = aptr[0];
    int b = blockIdx.y;
    int p = blockIdx.x * blockDim.x + t;
    if (p >= npix) return;
    const float* xb = x + (size_t)b * CCH * npix;
    float acc[COUT];
    #pragma unroll
    for (int o = 0; o < COUT; o++) acc[o] = bs[o];
    #pragma unroll
    for (int c = 0; c < CCH; c++) {
        float xv = xb[(size_t)c*npix + p];
        #pragma unroll
        for (int o = 0; o < COUT; o++) acc[o] = fmaf(xv, ws[o*CCH + c], acc[o]);
    }
    if (DST == 1) {           // channel-major
        float* ob = outg + (size_t)b * COUT * npix;
        #pragma unroll
        for (int o = 0; o < COUT; o++) {
            float v = acc[o];
            ob[(size_t)o*npix + p] = (v >= 0.f) ? v : a * v;
        }
    } else {                  // pixel-major [p][COUT]
        float* ob = outg + ((size_t)b * npix + p) * COUT;
        #pragma unroll
        for (int o = 0; o < COUT; o += 4) {
            float4 vv;
            vv.x = (acc[o+0] >= 0.f) ? acc[o+0] : a * acc[o+0];
            vv.y = (acc[o+1] >= 0.f) ? acc[o+1] : a * acc[o+1];
            vv.z = (acc[o+2] >= 0.f) ? acc[o+2] : a * acc[o+2];
            vv.w = (acc[o+3] >= 0.f) ? acc[o+3] : a * acc[o+3];
            *(float4*)(ob + o) = vv;
        }
    }
}

// ---------------- im2col 3x3 (same pad) for embed -> Rim ----------------
__global__ void im2col3k() {
    const int Cn = CCH, Ht = HSS, Wt = HSS;
    int idx = blockIdx.x * blockDim.x + threadIdx.x;
    int total = BB * Cn * Ht * Wt;
    if (idx >= total) return;
    int xq = idx % Wt; int tmp = idx / Wt;
    int yq = tmp % Ht; tmp /= Ht;
    int c  = tmp % Cn; int b = tmp / Cn;
    const float* s = g_embed + ((size_t)(b*Cn + c)) * Ht * Wt;
    float* d = g_Rim + ((size_t)b*Ht*Wt + (size_t)yq*Wt + xq) * (Cn*9) + c*9;
    #pragma unroll
    for (int i = 0; i < 3; i++) {
        int yy = yq + i - 1;
        #pragma unroll
        for (int j = 0; j < 3; j++) {
            int xx = xq + j - 1;
            float v = (yy >= 0 && yy < Ht && xx >= 0 && xx < Wt) ? s[yy*Wt + xx] : 0.f;
            d[i*3 + j] = v;
        }
    }
}

// ---------------- per-pixel channel energy + patch inv-norm ----------------
__global__ void n2_kernel() {
    int idx = blockIdx.x * blockDim.x + threadIdx.x;
    if (idx >= BB*LLN) return;
    const float* r = g_ref + (size_t)idx * CRR;
    float s = 0.f;
    #pragma unroll
    for (int c = 0; c < CRR; c += 4) {
        float4 v = *(const float4*)(r + c);
        s = fmaf(v.x, v.x, s); s = fmaf(v.y, v.y, s);
        s = fmaf(v.z, v.z, s); s = fmaf(v.w, v.w, s);
    }
    g_n2[idx] = s;
}

__global__ void invn_kernel() {
    int idx = blockIdx.x * blockDim.x + threadIdx.x;
    if (idx >= BB*LLN) return;
    int b = idx / LLN, l = idx % LLN;
    int ly = l / HSS, lx = l % HSS;
    const float* n2b = g_n2 + b*LLN;
    float s = 0.f;
    #pragma unroll
    for (int dy = -1; dy <= 1; dy++)
        #pragma unroll
        for (int dx = -1; dx <= 1; dx++) {
            int yy = ly + dy, xx = lx + dx;
            if (yy >= 0 && yy < HSS && xx >= 0 && xx < HSS)
                s += n2b[yy*HSS + xx];
        }
    g_invn[idx] = 1.f / fmaxf(sqrtf(s), 1e-4f);
}

// ---------------- Gram GEMM: D = match [M,32] * ref [N,32]^T ----------------
// M=9216, N=2304, K=32. 128x128 tile, 8x8 per thread.
__global__ void __launch_bounds__(256) gemmD_kernel() {
    const int M = HWP, N = LLN, K = CRR;
    int bz = blockIdx.z;
    const float* __restrict__ A  = g_match + (size_t)bz*M*K;
    const float* __restrict__ Bp = g_ref   + (size_t)bz*N*K;
    float* __restrict__ Dp = g_D + (size_t)bz*M*N;
    __shared__ float As[32][132];
    __shared__ float Bs[32][132];
    int t = threadIdx.x;
    int m0 = blockIdx.y * 128, n0 = blockIdx.x * 128;
    int lr = t >> 1, lc = (t & 1) * 16;
    int tx = t & 15, ty = t >> 4;
    #pragma unroll
    for (int q = 0; q < 4; q++) {
        float4 av = *(const float4*)(A  + (size_t)(m0+lr)*K + lc + q*4);
        As[lc+q*4+0][lr]=av.x; As[lc+q*4+1][lr]=av.y;
        As[lc+q*4+2][lr]=av.z; As[lc+q*4+3][lr]=av.w;
        float4 bv = *(const float4*)(Bp + (size_t)(n0+lr)*K + lc + q*4);
        Bs[lc+q*4+0][lr]=bv.x; Bs[lc+q*4+1][lr]=bv.y;
        Bs[lc+q*4+2][lr]=bv.z; Bs[lc+q*4+3][lr]=bv.w;
    }
    __syncthreads();
    float acc[8][8];
    #pragma unroll
    for (int i = 0; i < 8; i++)
        #pragma unroll
        for (int j = 0; j < 8; j++) acc[i][j] = 0.f;
    #pragma unroll 4
    for (int kk = 0; kk < 32; kk++) {
        float ar[8], br[8];
        #pragma unroll
        for (int i = 0; i < 8; i++) ar[i] = As[kk][ty*8 + i];
        #pragma unroll
        for (int j = 0; j < 8; j++) br[j] = Bs[kk][tx*8 + j];
        #pragma unroll
        for (int i = 0; i < 8; i++)
            #pragma unroll
            for (int j = 0; j < 8; j++) acc[i][j] = fmaf(ar[i], br[j], acc[i][j]);
    }
    #pragma unroll
    for (int i = 0; i < 8; i++) {
        float* dr = Dp + (size_t)(m0 + ty*8 + i)*N + n0 + tx*8;
        *(float4*)(dr)     = make_float4(acc[i][0], acc[i][1], acc[i][2], acc[i][3]);
        *(float4*)(dr + 4) = make_float4(acc[i][4], acc[i][5], acc[i][6], acc[i][7]);
    }
}

// ---------------- fused diagonal stencil + softmax ----------------
// logit[p,l] = invn[l] * sum_{d in 3x3} D[p+d, l+d]  (both-valid taps only),
// then softmax over l with SCALE=10, written to g_S.
__global__ void __launch_bounds__(256) logits_softmax_kernel() {
    int row = blockIdx.x;
    int b = row / HWP, p = row % HWP;
    int py = p / WWD, px = p % WWD;
    const float* __restrict__ Db = g_D + (size_t)b*HWP*LLN;
    const float* __restrict__ invn = g_invn + b*LLN;
    float* __restrict__ Sr = g_S + (size_t)row * LLN;

    const float* rp[9]; bool rv[9]; int co[9];
    #pragma unroll
    for (int dy = -1; dy <= 1; dy++)
        #pragma unroll
        for (int dx = -1; dx <= 1; dx++) {
            int k = (dy+1)*3 + (dx+1);
            int yy = py + dy, xx = px + dx;
            rv[k] = (yy >= 0 && yy < HH && xx >= 0 && xx < WWD);
            rp[k] = Db + (size_t)(yy*WWD + xx) * LLN;
            co[k] = dy*HSS + dx;
        }

    int t = threadIdx.x;
    float v[9]; float m = -1e30f;
    #pragma unroll
    for (int i = 0; i < 9; i++) {
        int l = i*256 + t;
        int ly = l / HSS, lx = l % HSS;
        float s = 0.f;
        #pragma unroll
        for (int dy = -1; dy <= 1; dy++)
            #pragma unroll
            for (int dx = -1; dx <= 1; dx++) {
                int k = (dy+1)*3 + (dx+1);
                int yy = ly + dy, xx = lx + dx;
                bool ok = rv[k] && (yy >= 0) && (yy < HSS) && (xx >= 0) && (xx < HSS);
                if (ok) s += rp[k][l + co[k]];
            }
        v[i] = 10.f * s * invn[l];
        m = fmaxf(m, v[i]);
    }
    __shared__ float red[256];
    red[t] = m; __syncthreads();
    #pragma unroll
    for (int s = 128; s > 0; s >>= 1) { if (t < s) red[t] = fmaxf(red[t], red[t+s]); __syncthreads(); }
    m = red[0];
    __syncthreads();
    float sum = 0.f;
    #pragma unroll
    for (int i = 0; i < 9; i++) { v[i] = __expf(v[i] - m); sum += v[i]; }
    red[t] = sum; __syncthreads();
    #pragma unroll
    for (int s = 128; s > 0; s >>= 1) { if (t < s) red[t] += red[t+s]; __syncthreads(); }
    float inv = 1.f / red[0];
    #pragma unroll
    for (int i = 0; i < 9; i++) Sr[i*256 + t] = v[i] * inv;
}

// ---------------- GEMM2 (tf32 tensor cores): P2 = S [M,K] * Rim [K,N] ----------------
// M=9216, K=2304, N=576. Block 128x64, 8 warps (4x2), warp tile 32x32,
// k-step 16, double-buffered smem. All dims divide exactly (no guards).
// Smem layouts (conflict-free fragment LDS):
//   As[s][m][k]: k-stride 20 words  -> frag bank = (20*gr + gc) % 32, all distinct
//   Bs[s][k][n]: n-stride 72 words  -> frag bank = (8*gc + gr) % 32, all distinct
__global__ void __launch_bounds__(256) gemm2_tf32_kernel() {
    const int N = NN2, K = LLN;
    int bz = blockIdx.z;
    const float* __restrict__ A  = g_S   + (size_t)bz*HWP*K;
    const float* __restrict__ Bp = g_Rim + (size_t)bz*K*N;
    float* __restrict__ Cp = g_P2 + (size_t)bz*HWP*N;

    __shared__ unsigned As[2][128][20];
    __shared__ unsigned Bs[2][16][72];

    int t = threadIdx.x;
    int m0 = blockIdx.y * 128, n0 = blockIdx.x * 64;
    int wid = t >> 5, lane = t & 31;
    int wr = wid & 3, wc = wid >> 2;      // warp grid 4 x 2
    int gr = lane >> 2, gc = lane & 3;

    // staging assignment
    int arow = t >> 2;            // 0..63  (and arow+64)
    int acol = (t & 3) * 4;       // 0,4,8,12
    int brow = t >> 4;            // 0..15
    int bcol = (t & 15) * 4;      // 0..60

    const float* aP0 = A  + (size_t)(m0 + arow)      * K + acol;
    const float* aP1 = A  + (size_t)(m0 + arow + 64) * K + acol;
    const float* bP  = Bp + (size_t)brow * N + n0 + bcol;

    float acc[2][4][4];
    #pragma unroll
    for (int mt = 0; mt < 2; mt++)
        #pragma unroll
        for (int nt = 0; nt < 4; nt++)
            #pragma unroll
            for (int q = 0; q < 4; q++) acc[mt][nt][q] = 0.f;

    float4 av0 = *(const float4*)(aP0);
    float4 av1 = *(const float4*)(aP1);
    float4 bv  = *(const float4*)(bP);

    // store stage 0
    {
        As[0][arow][acol+0]    = to_tf32(av0.x);
        As[0][arow][acol+1]    = to_tf32(av0.y);
        As[0][arow][acol+2]    = to_tf32(av0.z);
        As[0][arow][acol+3]    = to_tf32(av0.w);
        As[0][arow+64][acol+0] = to_tf32(av1.x);
        As[0][arow+64][acol+1] = to_tf32(av1.y);
        As[0][arow+64][acol+2] = to_tf32(av1.z);
        As[0][arow+64][acol+3] = to_tf32(av1.w);
        uint4 bq;
        bq.x = to_tf32(bv.x); bq.y = to_tf32(bv.y);
        bq.z = to_tf32(bv.z); bq.w = to_tf32(bv.w);
        *(uint4*)&Bs[0][brow][bcol] = bq;
    }
    __syncthreads();

    const int KT = K / 16;   // 144
    for (int kt = 0; kt < KT; kt++) {
        if (kt + 1 < KT) {
            av0 = *(const float4*)(aP0 + (kt+1)*16);
            av1 = *(const float4*)(aP1 + (kt+1)*16);
            bv  = *(const float4*)(bP + (size_t)(kt+1)*16*N);
        }
        int s = kt & 1;
        int mb0 = wr*32, nb0 = wc*32;
        #pragma unroll
        for (int kh = 0; kh < 2; kh++) {
            int kb = kh * 8;
            unsigned af[2][4];
            #pragma unroll
            for (int mt = 0; mt < 2; mt++) {
                int mb = mb0 + mt*16;
                af[mt][0] = As[s][mb + gr    ][kb + gc];
                af[mt][1] = As[s][mb + gr + 8][kb + gc];
                af[mt][2] = As[s][mb + gr    ][kb + gc + 4];
                af[mt][3] = As[s][mb + gr + 8][kb + gc + 4];
            }
            unsigned bf[4][2];
            #pragma unroll
            for (int nt = 0; nt < 4; nt++) {
                int nb = nb0 + nt*8;
                bf[nt][0] = Bs[s][kb + gc    ][nb + gr];
                bf[nt][1] = Bs[s][kb + gc + 4][nb + gr];
            }
            #pragma unroll
            for (int mt = 0; mt < 2; mt++)
                #pragma unroll
                for (int nt = 0; nt < 4; nt++) {
                    asm volatile(
                        "mma.sync.aligned.m16n8k8.row.col.f32.tf32.tf32.f32 "
                        "{%0,%1,%2,%3}, {%4,%5,%6,%7}, {%8,%9}, {%0,%1,%2,%3};"
                        : "+f"(acc[mt][nt][0]), "+f"(acc[mt][nt][1]),
                          "+f"(acc[mt][nt][2]), "+f"(acc[mt][nt][3])
                        : "r"(af[mt][0]), "r"(af[mt][1]), "r"(af[mt][2]), "r"(af[mt][3]),
                          "r"(bf[nt][0]), "r"(bf[nt][1]));
                }
        }
        if (kt + 1 < KT) {
            int s2 = (kt + 1) & 1;
            As[s2][arow][acol+0]    = to_tf32(av0.x);
            As[s2][arow][acol+1]    = to_tf32(av0.y);
            As[s2][arow][acol+2]    = to_tf32(av0.z);
            As[s2][arow][acol+3]    = to_tf32(av0.w);
            As[s2][arow+64][acol+0] = to_tf32(av1.x);
            As[s2][arow+64][acol+1] = to_tf32(av1.y);
            As[s2][arow+64][acol+2] = to_tf32(av1.z);
            As[s2][arow+64][acol+3] = to_tf32(av1.w);
            uint4 bq;
            bq.x = to_tf32(bv.x); bq.y = to_tf32(bv.y);
            bq.z = to_tf32(bv.z); bq.w = to_tf32(bv.w);
            *(uint4*)&Bs[s2][brow][bcol] = bq;
        }
        __syncthreads();
    }

    // epilogue
    #pragma unroll
    for (int mt = 0; mt < 2; mt++) {
        int row = m0 + wr*32 + mt*16 + gr;
        #pragma unroll
        for (int nt = 0; nt < 4; nt++) {
            int col = n0 + wc*32 + nt*8 + 2*gc;
            *(float2*)(Cp + (size_t)row*N + col) =
                make_float2(acc[mt][nt][0], acc[mt][nt][1]);
            *(float2*)(Cp + (size_t)(row+8)*N + col) =
                make_float2(acc[mt][nt][2], acc[mt][nt][3]);
        }
    }
}

// ---------------- stride-2 transpose-conv gather ----------------
__global__ void gather_kernel(float* __restrict__ out) {
    long idx = (long)blockIdx.x * blockDim.x + threadIdx.x;
    const long total = (long)BB * CCH * HO * HO;
    if (idx >= total) return;
    int X = (int)(idx % HO); long tmp = idx / HO;
    int Y = (int)(tmp % HO); tmp /= HO;
    int c = (int)(tmp % CCH); int b = (int)(tmp / CCH);
    const float* __restrict__ Pb = g_P2 + (size_t)b * HWP * NN2 + c*9;

    float s;
    if ((Y & 1) == 0 && (X & 1) == 0) {
        int p = (Y >> 1)*WWD + (X >> 1);
        s = Pb[(size_t)p*NN2 + 4];                       // kh=1,kw=1
    } else if ((Y & 1) == 0) {
        int p0 = (Y >> 1)*WWD + ((X-1) >> 1);
        int p1 = (Y >> 1)*WWD + ((X+1) >> 1);
        s = Pb[(size_t)p0*NN2 + 5] + Pb[(size_t)p1*NN2 + 3];   // kw=2 / kw=0
    } else if ((X & 1) == 0) {
        int p0 = ((Y-1) >> 1)*WWD + (X >> 1);
        int p1 = ((Y+1) >> 1)*WWD + (X >> 1);
        s = Pb[(size_t)p0*NN2 + 7] + Pb[(size_t)p1*NN2 + 1];   // kh=2 / kh=0
    } else {
        int ya = (Y-1) >> 1, yb = (Y+1) >> 1;
        int xa = (X-1) >> 1, xb = (X+1) >> 1;
        s = Pb[(size_t)(ya*WWD + xa)*NN2 + 8]
          + Pb[(size_t)(ya*WWD + xb)*NN2 + 6]
          + Pb[(size_t)(yb*WWD + xa)*NN2 + 2]
          + Pb[(size_t)(yb*WWD + xb)*NN2 + 0];
    }
    out[idx] = s * (1.f/6.f);
}

// ---------------- launch ----------------
extern "C" void kernel_launch(void* const* d_in, const int* in_sizes, int n_in,
                              void* d_out, int out_size) {
    const float* input = (const float*)d_in[0];
    const float* small = (const float*)d_in[1];
    const float* w1    = (const float*)d_in[2];
    const float* b1    = (const float*)d_in[3];
    const float* a1    = (const float*)d_in[4];
    const float* w2    = (const float*)d_in[5];
    const float* b2    = (const float*)d_in[6];
    const float* a2    = (const float*)d_in[7];
    const float* wa    = (const float*)d_in[8];
    const float* ba    = (const float*)d_in[9];
    const float* aa    = (const float*)d_in[10];
    float* out = (float*)d_out;

    conv1x1k<CRR, 0><<<dim3(HWP/256, BB), 256>>>(input, w1, b1, a1, HWP);
    conv1x1k<CCH, 1><<<dim3(LLN/256, BB), 256>>>(small, wa, ba, aa, LLN);
    conv1x1k<CRR, 2><<<dim3(LLN/256, BB), 256>>>(small, w2, b2, a2, LLN);

    im2col3k<<<(BB*CCH*LLN + 255)/256, 256>>>();
    n2_kernel<<<(BB*LLN + 255)/256, 256>>>();
    invn_kernel<<<(BB*LLN + 255)/256, 256>>>();

    gemmD_kernel<<<dim3(LLN/128, HWP/128, BB), 256>>>();
    logits_softmax_kernel<<<BB*HWP, 256>>>();
    gemm2_tf32_kernel<<<dim3(NN2/64, HWP/128, BB), 256>>>();

    gather_kernel<<<(int)(((long)BB*CCH*HO*HO + 255)/256), 256>>>(out);
}

// round 9
// speedup vs baseline: 2.2655x; 1.4692x over previous
#include <cuda_runtime.h>

// CrossScaleAttention — round 8.
// Changes vs R7 (3136us):
//  * GEMM2 rewritten with warp-level tensor-core mma.sync.m16n8k8.tf32
//    (FFMA2 was measured-neutral; GEMM2 was ~2.2ms on the scalar FMA pipe).
//    tf32 only on this GEMM; logits/softmax path stays full fp32.

#define BB   4
#define CCH  64           // C
#define CRR  32           // C/r
#define HH   96
#define WWD  96
#define HWP  (HH*WWD)     // 9216 pixels
#define HSS  48
#define LLN  (HSS*HSS)    // 2304 patches
#define NN2  (CCH*9)      // 576
#define HO   191

// ---- static scratch (no allocations allowed) ----
__device__ float g_match[BB*HWP*CRR];            //  4.7 MB  [b][p][c]
__device__ float g_ref  [BB*LLN*CRR];            //  1.2 MB  [b][l][c]
__device__ float g_embed[BB*CCH*LLN];            //  2.4 MB  [b][c][l]
__device__ float g_Rim  [BB*LLN*NN2];            // 21.2 MB  embed patches [b][l][c*9+t]
__device__ float g_D    [(size_t)BB*HWP*LLN];    // 340 MB   channel Gram matrix
__device__ float g_S    [(size_t)BB*HWP*LLN];    // 340 MB   softmax probs
__device__ float g_P2   [(size_t)BB*HWP*NN2];    // 85 MB    per-pixel mixed filters
__device__ float g_n2   [BB*LLN];
__device__ float g_invn [BB*LLN];

// ---- tf32 helper ----
__device__ __forceinline__ unsigned to_tf32(float x) {
    unsigned r;
    asm("cvt.rna.tf32.f32 %0, %1;" : "=r"(r) : "f"(x));
    return r;
}

// ---------------- conv1x1 + PReLU ----------------
// x: [B, 64, npix] -> DST 0: g_match [b][p][32] ; DST 1: g_embed [b][64][l] ;
//                     DST 2: g_ref   [b][l][32]
template<int COUT, int DST>
__global__ void __launch_bounds__(256) conv1x1k(
        const float* __restrict__ x, const float* __restrict__ wm,
        const float* __restrict__ bias, const float* __restrict__ aptr,
        int npix) {
    float* outg = (DST == 0) ? g_match : (DST == 1) ? g_embed : g_ref;
    __shared__ float ws[COUT*CCH];
    __shared__ float bs[COUT];
    int t = threadIdx.x;
    for (int i = t; i < COUT*CCH; i += blockDim.x) ws[i] = wm[i];
    if (t < COUT) bs[t] = bias[t];
    __syncthreads();
    float a = aptr[0];
    int b = blockIdx.y;
    int p = blockIdx.x * blockDim.x + t;
    if (p >= npix) return;
    const float* xb = x + (size_t)b * CCH * npix;
    float acc[COUT];
    #pragma unroll
    for (int o = 0; o < COUT; o++) acc[o] = bs[o];
    #pragma unroll
    for (int c = 0; c < CCH; c++) {
        float xv = xb[(size_t)c*npix + p];
        #pragma unroll
        for (int o = 0; o < COUT; o++) acc[o] = fmaf(xv, ws[o*CCH + c], acc[o]);
    }
    if (DST == 1) {           // channel-major
        float* ob = outg + (size_t)b * COUT * npix;
        #pragma unroll
        for (int o = 0; o < COUT; o++) {
            float v = acc[o];
            ob[(size_t)o*npix + p] = (v >= 0.f) ? v : a * v;
        }
    } else {                  // pixel-major [p][COUT]
        float* ob = outg + ((size_t)b * npix + p) * COUT;
        #pragma unroll
        for (int o = 0; o < COUT; o += 4) {
            float4 vv;
            vv.x = (acc[o+0] >= 0.f) ? acc[o+0] : a * acc[o+0];
            vv.y = (acc[o+1] >= 0.f) ? acc[o+1] : a * acc[o+1];
            vv.z = (acc[o+2] >= 0.f) ? acc[o+2] : a * acc[o+2];
            vv.w = (acc[o+3] >= 0.f) ? acc[o+3] : a * acc[o+3];
            *(float4*)(ob + o) = vv;
        }
    }
}

// ---------------- im2col 3x3 (same pad) for embed -> Rim ----------------
__global__ void im2col3k() {
    const int Cn = CCH, Ht = HSS, Wt = HSS;
    int idx = blockIdx.x * blockDim.x + threadIdx.x;
    int total = BB * Cn * Ht * Wt;
    if (idx >= total) return;
    int xq = idx % Wt; int tmp = idx / Wt;
    int yq = tmp % Ht; tmp /= Ht;
    int c  = tmp % Cn; int b = tmp / Cn;
    const float* s = g_embed + ((size_t)(b*Cn + c)) * Ht * Wt;
    float* d = g_Rim + ((size_t)b*Ht*Wt + (size_t)yq*Wt + xq) * (Cn*9) + c*9;
    #pragma unroll
    for (int i = 0; i < 3; i++) {
        int yy = yq + i - 1;
        #pragma unroll
        for (int j = 0; j < 3; j++) {
            int xx = xq + j - 1;
            float v = (yy >= 0 && yy < Ht && xx >= 0 && xx < Wt) ? s[yy*Wt + xx] : 0.f;
            d[i*3 + j] = v;
        }
    }
}

// ---------------- per-pixel channel energy + patch inv-norm ----------------
__global__ void n2_kernel() {
    int idx = blockIdx.x * blockDim.x + threadIdx.x;
    if (idx >= BB*LLN) return;
    const float* r = g_ref + (size_t)idx * CRR;
    float s = 0.f;
    #pragma unroll
    for (int c = 0; c < CRR; c += 4) {
        float4 v = *(const float4*)(r + c);
        s = fmaf(v.x, v.x, s); s = fmaf(v.y, v.y, s);
        s = fmaf(v.z, v.z, s); s = fmaf(v.w, v.w, s);
    }
    g_n2[idx] = s;
}

__global__ void invn_kernel() {
    int idx = blockIdx.x * blockDim.x + threadIdx.x;
    if (idx >= BB*LLN) return;
    int b = idx / LLN, l = idx % LLN;
    int ly = l / HSS, lx = l % HSS;
    const float* n2b = g_n2 + b*LLN;
    float s = 0.f;
    #pragma unroll
    for (int dy = -1; dy <= 1; dy++)
        #pragma unroll
        for (int dx = -1; dx <= 1; dx++) {
            int yy = ly + dy, xx = lx + dx;
            if (yy >= 0 && yy < HSS && xx >= 0 && xx < HSS)
                s += n2b[yy*HSS + xx];
        }
    g_invn[idx] = 1.f / fmaxf(sqrtf(s), 1e-4f);
}

// ---------------- Gram GEMM: D = match [M,32] * ref [N,32]^T ----------------
// M=9216, N=2304, K=32. 128x128 tile, 8x8 per thread.
__global__ void __launch_bounds__(256) gemmD_kernel() {
    const int M = HWP, N = LLN, K = CRR;
    int bz = blockIdx.z;
    const float* __restrict__ A  = g_match + (size_t)bz*M*K;
    const float* __restrict__ Bp = g_ref   + (size_t)bz*N*K;
    float* __restrict__ Dp = g_D + (size_t)bz*M*N;
    __shared__ float As[32][132];
    __shared__ float Bs[32][132];
    int t = threadIdx.x;
    int m0 = blockIdx.y * 128, n0 = blockIdx.x * 128;
    int lr = t >> 1, lc = (t & 1) * 16;
    int tx = t & 15, ty = t >> 4;
    #pragma unroll
    for (int q = 0; q < 4; q++) {
        float4 av = *(const float4*)(A  + (size_t)(m0+lr)*K + lc + q*4);
        As[lc+q*4+0][lr]=av.x; As[lc+q*4+1][lr]=av.y;
        As[lc+q*4+2][lr]=av.z; As[lc+q*4+3][lr]=av.w;
        float4 bv = *(const float4*)(Bp + (size_t)(n0+lr)*K + lc + q*4);
        Bs[lc+q*4+0][lr]=bv.x; Bs[lc+q*4+1][lr]=bv.y;
        Bs[lc+q*4+2][lr]=bv.z; Bs[lc+q*4+3][lr]=bv.w;
    }
    __syncthreads();
    float acc[8][8];
    #pragma unroll
    for (int i = 0; i < 8; i++)
        #pragma unroll
        for (int j = 0; j < 8; j++) acc[i][j] = 0.f;
    #pragma unroll 4
    for (int kk = 0; kk < 32; kk++) {
        float ar[8], br[8];
        #pragma unroll
        for (int i = 0; i < 8; i++) ar[i] = As[kk][ty*8 + i];
        #pragma unroll
        for (int j = 0; j < 8; j++) br[j] = Bs[kk][tx*8 + j];
        #pragma unroll
        for (int i = 0; i < 8; i++)
            #pragma unroll
            for (int j = 0; j < 8; j++) acc[i][j] = fmaf(ar[i], br[j], acc[i][j]);
    }
    #pragma unroll
    for (int i = 0; i < 8; i++) {
        float* dr = Dp + (size_t)(m0 + ty*8 + i)*N + n0 + tx*8;
        *(float4*)(dr)     = make_float4(acc[i][0], acc[i][1], acc[i][2], acc[i][3]);
        *(float4*)(dr + 4) = make_float4(acc[i][4], acc[i][5], acc[i][6], acc[i][7]);
    }
}

// ---------------- fused diagonal stencil + softmax ----------------
// logit[p,l] = invn[l] * sum_{d in 3x3} D[p+d, l+d]  (both-valid taps only),
// then softmax over l with SCALE=10, written to g_S.
__global__ void __launch_bounds__(256) logits_softmax_kernel() {
    int row = blockIdx.x;
    int b = row / HWP, p = row % HWP;
    int py = p / WWD, px = p % WWD;
    const float* __restrict__ Db = g_D + (size_t)b*HWP*LLN;
    const float* __restrict__ invn = g_invn + b*LLN;
    float* __restrict__ Sr = g_S + (size_t)row * LLN;

    const float* rp[9]; bool rv[9]; int co[9];
    #pragma unroll
    for (int dy = -1; dy <= 1; dy++)
        #pragma unroll
        for (int dx = -1; dx <= 1; dx++) {
            int k = (dy+1)*3 + (dx+1);
            int yy = py + dy, xx = px + dx;
            rv[k] = (yy >= 0 && yy < HH && xx >= 0 && xx < WWD);
            rp[k] = Db + (size_t)(yy*WWD + xx) * LLN;
            co[k] = dy*HSS + dx;
        }

    int t = threadIdx.x;
    float v[9]; float m = -1e30f;
    #pragma unroll
    for (int i = 0; i < 9; i++) {
        int l = i*256 + t;
        int ly = l / HSS, lx = l % HSS;
        float s = 0.f;
        #pragma unroll
        for (int dy = -1; dy <= 1; dy++)
            #pragma unroll
            for (int dx = -1; dx <= 1; dx++) {
                int k = (dy+1)*3 + (dx+1);
                int yy = ly + dy, xx = lx + dx;
                bool ok = rv[k] && (yy >= 0) && (yy < HSS) && (xx >= 0) && (xx < HSS);
                if (ok) s += rp[k][l + co[k]];
            }
        v[i] = 10.f * s * invn[l];
        m = fmaxf(m, v[i]);
    }
    __shared__ float red[256];
    red[t] = m; __syncthreads();
    #pragma unroll
    for (int s = 128; s > 0; s >>= 1) { if (t < s) red[t] = fmaxf(red[t], red[t+s]); __syncthreads(); }
    m = red[0];
    __syncthreads();
    float sum = 0.f;
    #pragma unroll
    for (int i = 0; i < 9; i++) { v[i] = __expf(v[i] - m); sum += v[i]; }
    red[t] = sum; __syncthreads();
    #pragma unroll
    for (int s = 128; s > 0; s >>= 1) { if (t < s) red[t] += red[t+s]; __syncthreads(); }
    float inv = 1.f / red[0];
    #pragma unroll
    for (int i = 0; i < 9; i++) Sr[i*256 + t] = v[i] * inv;
}

// ---------------- GEMM2 (tf32 tensor cores): P2 = S [M,K] * Rim [K,N] ----------------
// M=9216, K=2304, N=576. Block 128x64, 8 warps (4x2), warp tile 32x32,
// k-step 16, double-buffered smem. All dims divide exactly (no guards).
// Smem layouts (conflict-free fragment LDS):
//   As[s][m][k]: k-stride 20 words  -> frag bank = (20*gr + gc) % 32, all distinct
//   Bs[s][k][n]: n-stride 72 words  -> frag bank = (8*gc + gr) % 32, all distinct
__global__ void __launch_bounds__(256) gemm2_tf32_kernel() {
    const int N = NN2, K = LLN;
    int bz = blockIdx.z;
    const float* __restrict__ A  = g_S   + (size_t)bz*HWP*K;
    const float* __restrict__ Bp = g_Rim + (size_t)bz*K*N;
    float* __restrict__ Cp = g_P2 + (size_t)bz*HWP*N;

    __shared__ unsigned As[2][128][20];
    __shared__ unsigned Bs[2][16][72];

    int t = threadIdx.x;
    int m0 = blockIdx.y * 128, n0 = blockIdx.x * 64;
    int wid = t >> 5, lane = t & 31;
    int wr = wid & 3, wc = wid >> 2;      // warp grid 4 x 2
    int gr = lane >> 2, gc = lane & 3;

    // staging assignment
    int arow = t >> 2;            // 0..63  (and arow+64)
    int acol = (t & 3) * 4;       // 0,4,8,12
    int brow = t >> 4;            // 0..15
    int bcol = (t & 15) * 4;      // 0..60

    const float* aP0 = A  + (size_t)(m0 + arow)      * K + acol;
    const float* aP1 = A  + (size_t)(m0 + arow + 64) * K + acol;
    const float* bP  = Bp + (size_t)brow * N + n0 + bcol;

    float acc[2][4][4];
    #pragma unroll
    for (int mt = 0; mt < 2; mt++)
        #pragma unroll
        for (int nt = 0; nt < 4; nt++)
            #pragma unroll
            for (int q = 0; q < 4; q++) acc[mt][nt][q] = 0.f;

    float4 av0 = *(const float4*)(aP0);
    float4 av1 = *(const float4*)(aP1);
    float4 bv  = *(const float4*)(bP);

    // store stage 0
    {
        As[0][arow][acol+0]    = to_tf32(av0.x);
        As[0][arow][acol+1]    = to_tf32(av0.y);
        As[0][arow][acol+2]    = to_tf32(av0.z);
        As[0][arow][acol+3]    = to_tf32(av0.w);
        As[0][arow+64][acol+0] = to_tf32(av1.x);
        As[0][arow+64][acol+1] = to_tf32(av1.y);
        As[0][arow+64][acol+2] = to_tf32(av1.z);
        As[0][arow+64][acol+3] = to_tf32(av1.w);
        uint4 bq;
        bq.x = to_tf32(bv.x); bq.y = to_tf32(bv.y);
        bq.z = to_tf32(bv.z); bq.w = to_tf32(bv.w);
        *(uint4*)&Bs[0][brow][bcol] = bq;
    }
    __syncthreads();

    const int KT = K / 16;   // 144
    for (int kt = 0; kt < KT; kt++) {
        if (kt + 1 < KT) {
            av0 = *(const float4*)(aP0 + (kt+1)*16);
            av1 = *(const float4*)(aP1 + (kt+1)*16);
            bv  = *(const float4*)(bP + (size_t)(kt+1)*16*N);
        }
        int s = kt & 1;
        int mb0 = wr*32, nb0 = wc*32;
        #pragma unroll
        for (int kh = 0; kh < 2; kh++) {
            int kb = kh * 8;
            unsigned af[2][4];
            #pragma unroll
            for (int mt = 0; mt < 2; mt++) {
                int mb = mb0 + mt*16;
                af[mt][0] = As[s][mb + gr    ][kb + gc];
                af[mt][1] = As[s][mb + gr + 8][kb + gc];
                af[mt][2] = As[s][mb + gr    ][kb + gc + 4];
                af[mt][3] = As[s][mb + gr + 8][kb + gc + 4];
            }
            unsigned bf[4][2];
            #pragma unroll
            for (int nt = 0; nt < 4; nt++) {
                int nb = nb0 + nt*8;
                bf[nt][0] = Bs[s][kb + gc    ][nb + gr];
                bf[nt][1] = Bs[s][kb + gc + 4][nb + gr];
            }
            #pragma unroll
            for (int mt = 0; mt < 2; mt++)
                #pragma unroll
                for (int nt = 0; nt < 4; nt++) {
                    asm volatile(
                        "mma.sync.aligned.m16n8k8.row.col.f32.tf32.tf32.f32 "
                        "{%0,%1,%2,%3}, {%4,%5,%6,%7}, {%8,%9}, {%0,%1,%2,%3};"
                        : "+f"(acc[mt][nt][0]), "+f"(acc[mt][nt][1]),
                          "+f"(acc[mt][nt][2]), "+f"(acc[mt][nt][3])
                        : "r"(af[mt][0]), "r"(af[mt][1]), "r"(af[mt][2]), "r"(af[mt][3]),
                          "r"(bf[nt][0]), "r"(bf[nt][1]));
                }
        }
        if (kt + 1 < KT) {
            int s2 = (kt + 1) & 1;
            As[s2][arow][acol+0]    = to_tf32(av0.x);
            As[s2][arow][acol+1]    = to_tf32(av0.y);
            As[s2][arow][acol+2]    = to_tf32(av0.z);
            As[s2][arow][acol+3]    = to_tf32(av0.w);
            As[s2][arow+64][acol+0] = to_tf32(av1.x);
            As[s2][arow+64][acol+1] = to_tf32(av1.y);
            As[s2][arow+64][acol+2] = to_tf32(av1.z);
            As[s2][arow+64][acol+3] = to_tf32(av1.w);
            uint4 bq;
            bq.x = to_tf32(bv.x); bq.y = to_tf32(bv.y);
            bq.z = to_tf32(bv.z); bq.w = to_tf32(bv.w);
            *(uint4*)&Bs[s2][brow][bcol] = bq;
        }
        __syncthreads();
    }

    // epilogue
    #pragma unroll
    for (int mt = 0; mt < 2; mt++) {
        int row = m0 + wr*32 + mt*16 + gr;
        #pragma unroll
        for (int nt = 0; nt < 4; nt++) {
            int col = n0 + wc*32 + nt*8 + 2*gc;
            *(float2*)(Cp + (size_t)row*N + col) =
                make_float2(acc[mt][nt][0], acc[mt][nt][1]);
            *(float2*)(Cp + (size_t)(row+8)*N + col) =
                make_float2(acc[mt][nt][2], acc[mt][nt][3]);
        }
    }
}

// ---------------- stride-2 transpose-conv gather ----------------
__global__ void gather_kernel(float* __restrict__ out) {
    long idx = (long)blockIdx.x * blockDim.x + threadIdx.x;
    const long total = (long)BB * CCH * HO * HO;
    if (idx >= total) return;
    int X = (int)(idx % HO); long tmp = idx / HO;
    int Y = (int)(tmp % HO); tmp /= HO;
    int c = (int)(tmp % CCH); int b = (int)(tmp / CCH);
    const float* __restrict__ Pb = g_P2 + (size_t)b * HWP * NN2 + c*9;

    float s;
    if ((Y & 1) == 0 && (X & 1) == 0) {
        int p = (Y >> 1)*WWD + (X >> 1);
        s = Pb[(size_t)p*NN2 + 4];                       // kh=1,kw=1
    } else if ((Y & 1) == 0) {
        int p0 = (Y >> 1)*WWD + ((X-1) >> 1);
        int p1 = (Y >> 1)*WWD + ((X+1) >> 1);
        s = Pb[(size_t)p0*NN2 + 5] + Pb[(size_t)p1*NN2 + 3];   // kw=2 / kw=0
    } else if ((X & 1) == 0) {
        int p0 = ((Y-1) >> 1)*WWD + (X >> 1);
        int p1 = ((Y+1) >> 1)*WWD + (X >> 1);
        s = Pb[(size_t)p0*NN2 + 7] + Pb[(size_t)p1*NN2 + 1];   // kh=2 / kh=0
    } else {
        int ya = (Y-1) >> 1, yb = (Y+1) >> 1;
        int xa = (X-1) >> 1, xb = (X+1) >> 1;
        s = Pb[(size_t)(ya*WWD + xa)*NN2 + 8]
          + Pb[(size_t)(ya*WWD + xb)*NN2 + 6]
          + Pb[(size_t)(yb*WWD + xa)*NN2 + 2]
          + Pb[(size_t)(yb*WWD + xb)*NN2 + 0];
    }
    out[idx] = s * (1.f/6.f);
}

// ---------------- launch ----------------
extern "C" void kernel_launch(void* const* d_in, const int* in_sizes, int n_in,
                              void* d_out, int out_size) {
    const float* input = (const float*)d_in[0];
    const float* small = (const float*)d_in[1];
    const float* w1    = (const float*)d_in[2];
    const float* b1    = (const float*)d_in[3];
    const float* a1    = (const float*)d_in[4];
    const float* w2    = (const float*)d_in[5];
    const float* b2    = (const float*)d_in[6];
    const float* a2    = (const float*)d_in[7];
    const float* wa    = (const float*)d_in[8];
    const float* ba    = (const float*)d_in[9];
    const float* aa    = (const float*)d_in[10];
    float* out = (float*)d_out;

    conv1x1k<CRR, 0><<<dim3(HWP/256, BB), 256>>>(input, w1, b1, a1, HWP);
    conv1x1k<CCH, 1><<<dim3(LLN/256, BB), 256>>>(small, wa, ba, aa, LLN);
    conv1x1k<CRR, 2><<<dim3(LLN/256, BB), 256>>>(small, w2, b2, a2, LLN);

    im2col3k<<<(BB*CCH*LLN + 255)/256, 256>>>();
    n2_kernel<<<(BB*LLN + 255)/256, 256>>>();
    invn_kernel<<<(BB*LLN + 255)/256, 256>>>();

    gemmD_kernel<<<dim3(LLN/128, HWP/128, BB), 256>>>();
    logits_softmax_kernel<<<BB*HWP, 256>>>();
    gemm2_tf32_kernel<<<dim3(NN2/64, HWP/128, BB), 256>>>();

    gather_kernel<<<(int)(((long)BB*CCH*HO*HO + 255)/256), 256>>>(out);
}

// round 10
// speedup vs baseline: 2.2829x; 1.0077x over previous
#include <cuda_runtime.h>

// CrossScaleAttention — round 8.
// Changes vs R7 (3136us):
//  * GEMM2 rewritten with warp-level tensor-core mma.sync.m16n8k8.tf32
//    (FFMA2 was measured-neutral; GEMM2 was ~2.2ms on the scalar FMA pipe).
//    tf32 only on this GEMM; logits/softmax path stays full fp32.

#define BB   4
#define CCH  64           // C
#define CRR  32           // C/r
#define HH   96
#define WWD  96
#define HWP  (HH*WWD)     // 9216 pixels
#define HSS  48
#define LLN  (HSS*HSS)    // 2304 patches
#define NN2  (CCH*9)      // 576
#define HO   191

// ---- static scratch (no allocations allowed) ----
__device__ float g_match[BB*HWP*CRR];            //  4.7 MB  [b][p][c]
__device__ float g_ref  [BB*LLN*CRR];            //  1.2 MB  [b][l][c]
__device__ float g_embed[BB*CCH*LLN];            //  2.4 MB  [b][c][l]
__device__ float g_Rim  [BB*LLN*NN2];            // 21.2 MB  embed patches [b][l][c*9+t]
__device__ float g_D    [(size_t)BB*HWP*LLN];    // 340 MB   channel Gram matrix
__device__ float g_S    [(size_t)BB*HWP*LLN];    // 340 MB   softmax probs
__device__ float g_P2   [(size_t)BB*HWP*NN2];    // 85 MB    per-pixel mixed filters
__device__ float g_n2   [BB*LLN];
__device__ float g_invn [BB*LLN];

// ---- tf32 helper ----
__device__ __forceinline__ unsigned to_tf32(float x) {
    unsigned r;
    asm("cvt.rna.tf32.f32 %0, %1;" : "=r"(r) : "f"(x));
    return r;
}

// ---------------- conv1x1 + PReLU ----------------
// x: [B, 64, npix] -> DST 0: g_match [b][p][32] ; DST 1: g_embed [b][64][l] ;
//                     DST 2: g_ref   [b][l][32]
template<int COUT, int DST>
__global__ void __launch_bounds__(256) conv1x1k(
        const float* __restrict__ x, const float* __restrict__ wm,
        const float* __restrict__ bias, const float* __restrict__ aptr,
        int npix) {
    float* outg = (DST == 0) ? g_match : (DST == 1) ? g_embed : g_ref;
    __shared__ float ws[COUT*CCH];
    __shared__ float bs[COUT];
    int t = threadIdx.x;
    for (int i = t; i < COUT*CCH; i += blockDim.x) ws[i] = wm[i];
    if (t < COUT) bs[t] = bias[t];
    __syncthreads();
    float a = aptr[0];
    int b = blockIdx.y;
    int p = blockIdx.x * blockDim.x + t;
    if (p >= npix) return;
    const float* xb = x + (size_t)b * CCH * npix;
    float acc[COUT];
    #pragma unroll
    for (int o = 0; o < COUT; o++) acc[o] = bs[o];
    #pragma unroll
    for (int c = 0; c < CCH; c++) {
        float xv = xb[(size_t)c*npix + p];
        #pragma unroll
        for (int o = 0; o < COUT; o++) acc[o] = fmaf(xv, ws[o*CCH + c], acc[o]);
    }
    if (DST == 1) {           // channel-major
        float* ob = outg + (size_t)b * COUT * npix;
        #pragma unroll
        for (int o = 0; o < COUT; o++) {
            float v = acc[o];
            ob[(size_t)o*npix + p] = (v >= 0.f) ? v : a * v;
        }
    } else {                  // pixel-major [p][COUT]
        float* ob = outg + ((size_t)b * npix + p) * COUT;
        #pragma unroll
        for (int o = 0; o < COUT; o += 4) {
            float4 vv;
            vv.x = (acc[o+0] >= 0.f) ? acc[o+0] : a * acc[o+0];
            vv.y = (acc[o+1] >= 0.f) ? acc[o+1] : a * acc[o+1];
            vv.z = (acc[o+2] >= 0.f) ? acc[o+2] : a * acc[o+2];
            vv.w = (acc[o+3] >= 0.f) ? acc[o+3] : a * acc[o+3];
            *(float4*)(ob + o) = vv;
        }
    }
}

// ---------------- im2col 3x3 (same pad) for embed -> Rim ----------------
__global__ void im2col3k() {
    const int Cn = CCH, Ht = HSS, Wt = HSS;
    int idx = blockIdx.x * blockDim.x + threadIdx.x;
    int total = BB * Cn * Ht * Wt;
    if (idx >= total) return;
    int xq = idx % Wt; int tmp = idx / Wt;
    int yq = tmp % Ht; tmp /= Ht;
    int c  = tmp % Cn; int b = tmp / Cn;
    const float* s = g_embed + ((size_t)(b*Cn + c)) * Ht * Wt;
    float* d = g_Rim + ((size_t)b*Ht*Wt + (size_t)yq*Wt + xq) * (Cn*9) + c*9;
    #pragma unroll
    for (int i = 0; i < 3; i++) {
        int yy = yq + i - 1;
        #pragma unroll
        for (int j = 0; j < 3; j++) {
            int xx = xq + j - 1;
            float v = (yy >= 0 && yy < Ht && xx >= 0 && xx < Wt) ? s[yy*Wt + xx] : 0.f;
            d[i*3 + j] = v;
        }
    }
}

// ---------------- per-pixel channel energy + patch inv-norm ----------------
__global__ void n2_kernel() {
    int idx = blockIdx.x * blockDim.x + threadIdx.x;
    if (idx >= BB*LLN) return;
    const float* r = g_ref + (size_t)idx * CRR;
    float s = 0.f;
    #pragma unroll
    for (int c = 0; c < CRR; c += 4) {
        float4 v = *(const float4*)(r + c);
        s = fmaf(v.x, v.x, s); s = fmaf(v.y, v.y, s);
        s = fmaf(v.z, v.z, s); s = fmaf(v.w, v.w, s);
    }
    g_n2[idx] = s;
}

__global__ void invn_kernel() {
    int idx = blockIdx.x * blockDim.x + threadIdx.x;
    if (idx >= BB*LLN) return;
    int b = idx / LLN, l = idx % LLN;
    int ly = l / HSS, lx = l % HSS;
    const float* n2b = g_n2 + b*LLN;
    float s = 0.f;
    #pragma unroll
    for (int dy = -1; dy <= 1; dy++)
        #pragma unroll
        for (int dx = -1; dx <= 1; dx++) {
            int yy = ly + dy, xx = lx + dx;
            if (yy >= 0 && yy < HSS && xx >= 0 && xx < HSS)
                s += n2b[yy*HSS + xx];
        }
    g_invn[idx] = 1.f / fmaxf(sqrtf(s), 1e-4f);
}

// ---------------- Gram GEMM: D = match [M,32] * ref [N,32]^T ----------------
// M=9216, N=2304, K=32. 128x128 tile, 8x8 per thread.
__global__ void __launch_bounds__(256) gemmD_kernel() {
    const int M = HWP, N = LLN, K = CRR;
    int bz = blockIdx.z;
    const float* __restrict__ A  = g_match + (size_t)bz*M*K;
    const float* __restrict__ Bp = g_ref   + (size_t)bz*N*K;
    float* __restrict__ Dp = g_D + (size_t)bz*M*N;
    __shared__ float As[32][132];
    __shared__ float Bs[32][132];
    int t = threadIdx.x;
    int m0 = blockIdx.y * 128, n0 = blockIdx.x * 128;
    int lr = t >> 1, lc = (t & 1) * 16;
    int tx = t & 15, ty = t >> 4;
    #pragma unroll
    for (int q = 0; q < 4; q++) {
        float4 av = *(const float4*)(A  + (size_t)(m0+lr)*K + lc + q*4);
        As[lc+q*4+0][lr]=av.x; As[lc+q*4+1][lr]=av.y;
        As[lc+q*4+2][lr]=av.z; As[lc+q*4+3][lr]=av.w;
        float4 bv = *(const float4*)(Bp + (size_t)(n0+lr)*K + lc + q*4);
        Bs[lc+q*4+0][lr]=bv.x; Bs[lc+q*4+1][lr]=bv.y;
        Bs[lc+q*4+2][lr]=bv.z; Bs[lc+q*4+3][lr]=bv.w;
    }
    __syncthreads();
    float acc[8][8];
    #pragma unroll
    for (int i = 0; i < 8; i++)
        #pragma unroll
        for (int j = 0; j < 8; j++) acc[i][j] = 0.f;
    #pragma unroll 4
    for (int kk = 0; kk < 32; kk++) {
        float ar[8], br[8];
        #pragma unroll
        for (int i = 0; i < 8; i++) ar[i] = As[kk][ty*8 + i];
        #pragma unroll
        for (int j = 0; j < 8; j++) br[j] = Bs[kk][tx*8 + j];
        #pragma unroll
        for (int i = 0; i < 8; i++)
            #pragma unroll
            for (int j = 0; j < 8; j++) acc[i][j] = fmaf(ar[i], br[j], acc[i][j]);
    }
    #pragma unroll
    for (int i = 0; i < 8; i++) {
        float* dr = Dp + (size_t)(m0 + ty*8 + i)*N + n0 + tx*8;
        *(float4*)(dr)     = make_float4(acc[i][0], acc[i][1], acc[i][2], acc[i][3]);
        *(float4*)(dr + 4) = make_float4(acc[i][4], acc[i][5], acc[i][6], acc[i][7]);
    }
}

// ---------------- fused diagonal stencil + softmax ----------------
// logit[p,l] = invn[l] * sum_{d in 3x3} D[p+d, l+d]  (both-valid taps only),
// then softmax over l with SCALE=10, written to g_S.
__global__ void __launch_bounds__(256) logits_softmax_kernel() {
    int row = blockIdx.x;
    int b = row / HWP, p = row % HWP;
    int py = p / WWD, px = p % WWD;
    const float* __restrict__ Db = g_D + (size_t)b*HWP*LLN;
    const float* __restrict__ invn = g_invn + b*LLN;
    float* __restrict__ Sr = g_S + (size_t)row * LLN;

    const float* rp[9]; bool rv[9]; int co[9];
    #pragma unroll
    for (int dy = -1; dy <= 1; dy++)
        #pragma unroll
        for (int dx = -1; dx <= 1; dx++) {
            int k = (dy+1)*3 + (dx+1);
            int yy = py + dy, xx = px + dx;
            rv[k] = (yy >= 0 && yy < HH && xx >= 0 && xx < WWD);
            rp[k] = Db + (size_t)(yy*WWD + xx) * LLN;
            co[k] = dy*HSS + dx;
        }

    int t = threadIdx.x;
    float v[9]; float m = -1e30f;
    #pragma unroll
    for (int i = 0; i < 9; i++) {
        int l = i*256 + t;
        int ly = l / HSS, lx = l % HSS;
        float s = 0.f;
        #pragma unroll
        for (int dy = -1; dy <= 1; dy++)
            #pragma unroll
            for (int dx = -1; dx <= 1; dx++) {
                int k = (dy+1)*3 + (dx+1);
                int yy = ly + dy, xx = lx + dx;
                bool ok = rv[k] && (yy >= 0) && (yy < HSS) && (xx >= 0) && (xx < HSS);
                if (ok) s += rp[k][l + co[k]];
            }
        v[i] = 10.f * s * invn[l];
        m = fmaxf(m, v[i]);
    }
    __shared__ float red[256];
    red[t] = m; __syncthreads();
    #pragma unroll
    for (int s = 128; s > 0; s >>= 1) { if (t < s) red[t] = fmaxf(red[t], red[t+s]); __syncthreads(); }
    m = red[0];
    __syncthreads();
    float sum = 0.f;
    #pragma unroll
    for (int i = 0; i < 9; i++) { v[i] = __expf(v[i] - m); sum += v[i]; }
    red[t] = sum; __syncthreads();
    #pragma unroll
    for (int s = 128; s > 0; s >>= 1) { if (t < s) red[t] += red[t+s]; __syncthreads(); }
    float inv = 1.f / red[0];
    #pragma unroll
    for (int i = 0; i < 9; i++) Sr[i*256 + t] = v[i] * inv;
}

// ---------------- GEMM2 (tf32 tensor cores): P2 = S [M,K] * Rim [K,N] ----------------
// M=9216, K=2304, N=576. Block 128x64, 8 warps (4x2), warp tile 32x32,
// k-step 16, double-buffered smem. All dims divide exactly (no guards).
// Smem layouts (conflict-free fragment LDS):
//   As[s][m][k]: k-stride 20 words  -> frag bank = (20*gr + gc) % 32, all distinct
//   Bs[s][k][n]: n-stride 72 words  -> frag bank = (8*gc + gr) % 32, all distinct
__global__ void __launch_bounds__(256) gemm2_tf32_kernel() {
    const int N = NN2, K = LLN;
    int bz = blockIdx.z;
    const float* __restrict__ A  = g_S   + (size_t)bz*HWP*K;
    const float* __restrict__ Bp = g_Rim + (size_t)bz*K*N;
    float* __restrict__ Cp = g_P2 + (size_t)bz*HWP*N;

    __shared__ unsigned As[2][128][20];
    __shared__ unsigned Bs[2][16][72];

    int t = threadIdx.x;
    int m0 = blockIdx.y * 128, n0 = blockIdx.x * 64;
    int wid = t >> 5, lane = t & 31;
    int wr = wid & 3, wc = wid >> 2;      // warp grid 4 x 2
    int gr = lane >> 2, gc = lane & 3;

    // staging assignment
    int arow = t >> 2;            // 0..63  (and arow+64)
    int acol = (t & 3) * 4;       // 0,4,8,12
    int brow = t >> 4;            // 0..15
    int bcol = (t & 15) * 4;      // 0..60

    const float* aP0 = A  + (size_t)(m0 + arow)      * K + acol;
    const float* aP1 = A  + (size_t)(m0 + arow + 64) * K + acol;
    const float* bP  = Bp + (size_t)brow * N + n0 + bcol;

    float acc[2][4][4];
    #pragma unroll
    for (int mt = 0; mt < 2; mt++)
        #pragma unroll
        for (int nt = 0; nt < 4; nt++)
            #pragma unroll
            for (int q = 0; q < 4; q++) acc[mt][nt][q] = 0.f;

    float4 av0 = *(const float4*)(aP0);
    float4 av1 = *(const float4*)(aP1);
    float4 bv  = *(const float4*)(bP);

    // store stage 0
    {
        As[0][arow][acol+0]    = to_tf32(av0.x);
        As[0][arow][acol+1]    = to_tf32(av0.y);
        As[0][arow][acol+2]    = to_tf32(av0.z);
        As[0][arow][acol+3]    = to_tf32(av0.w);
        As[0][arow+64][acol+0] = to_tf32(av1.x);
        As[0][arow+64][acol+1] = to_tf32(av1.y);
        As[0][arow+64][acol+2] = to_tf32(av1.z);
        As[0][arow+64][acol+3] = to_tf32(av1.w);
        uint4 bq;
        bq.x = to_tf32(bv.x); bq.y = to_tf32(bv.y);
        bq.z = to_tf32(bv.z); bq.w = to_tf32(bv.w);
        *(uint4*)&Bs[0][brow][bcol] = bq;
    }
    __syncthreads();

    const int KT = K / 16;   // 144
    for (int kt = 0; kt < KT; kt++) {
        if (kt + 1 < KT) {
            av0 = *(const float4*)(aP0 + (kt+1)*16);
            av1 = *(const float4*)(aP1 + (kt+1)*16);
            bv  = *(const float4*)(bP + (size_t)(kt+1)*16*N);
        }
        int s = kt & 1;
        int mb0 = wr*32, nb0 = wc*32;
        #pragma unroll
        for (int kh = 0; kh < 2; kh++) {
            int kb = kh * 8;
            unsigned af[2][4];
            #pragma unroll
            for (int mt = 0; mt < 2; mt++) {
                int mb = mb0 + mt*16;
                af[mt][0] = As[s][mb + gr    ][kb + gc];
                af[mt][1] = As[s][mb + gr + 8][kb + gc];
                af[mt][2] = As[s][mb + gr    ][kb + gc + 4];
                af[mt][3] = As[s][mb + gr + 8][kb + gc + 4];
            }
            unsigned bf[4][2];
            #pragma unroll
            for (int nt = 0; nt < 4; nt++) {
                int nb = nb0 + nt*8;
                bf[nt][0] = Bs[s][kb + gc    ][nb + gr];
                bf[nt][1] = Bs[s][kb + gc + 4][nb + gr];
            }
            #pragma unroll
            for (int mt = 0; mt < 2; mt++)
                #pragma unroll
                for (int nt = 0; nt < 4; nt++) {
                    asm volatile(
                        "mma.sync.aligned.m16n8k8.row.col.f32.tf32.tf32.f32 "
                        "{%0,%1,%2,%3}, {%4,%5,%6,%7}, {%8,%9}, {%0,%1,%2,%3};"
                        : "+f"(acc[mt][nt][0]), "+f"(acc[mt][nt][1]),
                          "+f"(acc[mt][nt][2]), "+f"(acc[mt][nt][3])
                        : "r"(af[mt][0]), "r"(af[mt][1]), "r"(af[mt][2]), "r"(af[mt][3]),
                          "r"(bf[nt][0]), "r"(bf[nt][1]));
                }
        }
        if (kt + 1 < KT) {
            int s2 = (kt + 1) & 1;
            As[s2][arow][acol+0]    = to_tf32(av0.x);
            As[s2][arow][acol+1]    = to_tf32(av0.y);
            As[s2][arow][acol+2]    = to_tf32(av0.z);
            As[s2][arow][acol+3]    = to_tf32(av0.w);
            As[s2][arow+64][acol+0] = to_tf32(av1.x);
            As[s2][arow+64][acol+1] = to_tf32(av1.y);
            As[s2][arow+64][acol+2] = to_tf32(av1.z);
            As[s2][arow+64][acol+3] = to_tf32(av1.w);
            uint4 bq;
            bq.x = to_tf32(bv.x); bq.y = to_tf32(bv.y);
            bq.z = to_tf32(bv.z); bq.w = to_tf32(bv.w);
            *(uint4*)&Bs[s2][brow][bcol] = bq;
        }
        __syncthreads();
    }

    // epilogue
    #pragma unroll
    for (int mt = 0; mt < 2; mt++) {
        int row = m0 + wr*32 + mt*16 + gr;
        #pragma unroll
        for (int nt = 0; nt < 4; nt++) {
            int col = n0 + wc*32 + nt*8 + 2*gc;
            *(float2*)(Cp + (size_t)row*N + col) =
                make_float2(acc[mt][nt][0], acc[mt][nt][1]);
            *(float2*)(Cp + (size_t)(row+8)*N + col) =
                make_float2(acc[mt][nt][2], acc[mt][nt][3]);
        }
    }
}

// ---------------- stride-2 transpose-conv gather ----------------
__global__ void gather_kernel(float* __restrict__ out) {
    long idx = (long)blockIdx.x * blockDim.x + threadIdx.x;
    const long total = (long)BB * CCH * HO * HO;
    if (idx >= total) return;
    int X = (int)(idx % HO); long tmp = idx / HO;
    int Y = (int)(tmp % HO); tmp /= HO;
    int c = (int)(tmp % CCH); int b = (int)(tmp / CCH);
    const float* __restrict__ Pb = g_P2 + (size_t)b * HWP * NN2 + c*9;

    float s;
    if ((Y & 1) == 0 && (X & 1) == 0) {
        int p = (Y >> 1)*WWD + (X >> 1);
        s = Pb[(size_t)p*NN2 + 4];                       // kh=1,kw=1
    } else if ((Y & 1) == 0) {
        int p0 = (Y >> 1)*WWD + ((X-1) >> 1);
        int p1 = (Y >> 1)*WWD + ((X+1) >> 1);
        s = Pb[(size_t)p0*NN2 + 5] + Pb[(size_t)p1*NN2 + 3];   // kw=2 / kw=0
    } else if ((X & 1) == 0) {
        int p0 = ((Y-1) >> 1)*WWD + (X >> 1);
        int p1 = ((Y+1) >> 1)*WWD + (X >> 1);
        s = Pb[(size_t)p0*NN2 + 7] + Pb[(size_t)p1*NN2 + 1];   // kh=2 / kh=0
    } else {
        int ya = (Y-1) >> 1, yb = (Y+1) >> 1;
        int xa = (X-1) >> 1, xb = (X+1) >> 1;
        s = Pb[(size_t)(ya*WWD + xa)*NN2 + 8]
          + Pb[(size_t)(ya*WWD + xb)*NN2 + 6]
          + Pb[(size_t)(yb*WWD + xa)*NN2 + 2]
          + Pb[(size_t)(yb*WWD + xb)*NN2 + 0];
    }
    out[idx] = s * (1.f/6.f);
}

// ---------------- launch ----------------
extern "C" void kernel_launch(void* const* d_in, const int* in_sizes, int n_in,
                              void* d_out, int out_size) {
    const float* input = (const float*)d_in[0];
    const float* small = (const float*)d_in[1];
    const float* w1    = (const float*)d_in[2];
    const float* b1    = (const float*)d_in[3];
    const float* a1    = (const float*)d_in[4];
    const float* w2    = (const float*)d_in[5];
    const float* b2    = (const float*)d_in[6];
    const float* a2    = (const float*)d_in[7];
    const float* wa    = (const float*)d_in[8];
    const float* ba    = (const float*)d_in[9];
    const float* aa    = (const float*)d_in[10];
    float* out = (float*)d_out;

    conv1x1k<CRR, 0><<<dim3(HWP/256, BB), 256>>>(input, w1, b1, a1, HWP);
    conv1x1k<CCH, 1><<<dim3(LLN/256, BB), 256>>>(small, wa, ba, aa, LLN);
    conv1x1k<CRR, 2><<<dim3(LLN/256, BB), 256>>>(small, w2, b2, a2, LLN);

    im2col3k<<<(BB*CCH*LLN + 255)/256, 256>>>();
    n2_kernel<<<(BB*LLN + 255)/256, 256>>>();
    invn_kernel<<<(BB*LLN + 255)/256, 256>>>();

    gemmD_kernel<<<dim3(LLN/128, HWP/128, BB), 256>>>();
    logits_softmax_kernel<<<BB*HWP, 256>>>();
    gemm2_tf32_kernel<<<dim3(NN2/64, HWP/128, BB), 256>>>();

    gather_kernel<<<(int)(((long)BB*CCH*HO*HO + 255)/256), 256>>>(out);
}

// round 11
// speedup vs baseline: 2.2991x; 1.0071x over previous
#include <cuda_runtime.h>

// CrossScaleAttention — round 8.
// Changes vs R7 (3136us):
//  * GEMM2 rewritten with warp-level tensor-core mma.sync.m16n8k8.tf32
//    (FFMA2 was measured-neutral; GEMM2 was ~2.2ms on the scalar FMA pipe).
//    tf32 only on this GEMM; logits/softmax path stays full fp32.

#define BB   4
#define CCH  64           // C
#define CRR  32           // C/r
#define HH   96
#define WWD  96
#define HWP  (HH*WWD)     // 9216 pixels
#define HSS  48
#define LLN  (HSS*HSS)    // 2304 patches
#define NN2  (CCH*9)      // 576
#define HO   191

// ---- static scratch (no allocations allowed) ----
__device__ float g_match[BB*HWP*CRR];            //  4.7 MB  [b][p][c]
__device__ float g_ref  [BB*LLN*CRR];            //  1.2 MB  [b][l][c]
__device__ float g_embed[BB*CCH*LLN];            //  2.4 MB  [b][c][l]
__device__ float g_Rim  [BB*LLN*NN2];            // 21.2 MB  embed patches [b][l][c*9+t]
__device__ float g_D    [(size_t)BB*HWP*LLN];    // 340 MB   channel Gram matrix
__device__ float g_S    [(size_t)BB*HWP*LLN];    // 340 MB   softmax probs
__device__ float g_P2   [(size_t)BB*HWP*NN2];    // 85 MB    per-pixel mixed filters
__device__ float g_n2   [BB*LLN];
__device__ float g_invn [BB*LLN];

// ---- tf32 helper ----
__device__ __forceinline__ unsigned to_tf32(float x) {
    unsigned r;
    asm("cvt.rna.tf32.f32 %0, %1;" : "=r"(r) : "f"(x));
    return r;
}

// ---------------- conv1x1 + PReLU ----------------
// x: [B, 64, npix] -> DST 0: g_match [b][p][32] ; DST 1: g_embed [b][64][l] ;
//                     DST 2: g_ref   [b][l][32]
template<int COUT, int DST>
__global__ void __launch_bounds__(256) conv1x1k(
        const float* __restrict__ x, const float* __restrict__ wm,
        const float* __restrict__ bias, const float* __restrict__ aptr,
        int npix) {
    float* outg = (DST == 0) ? g_match : (DST == 1) ? g_embed : g_ref;
    __shared__ float ws[COUT*CCH];
    __shared__ float bs[COUT];
    int t = threadIdx.x;
    for (int i = t; i < COUT*CCH; i += blockDim.x) ws[i] = wm[i];
    if (t < COUT) bs[t] = bias[t];
    __syncthreads();
    float a = aptr[0];
    int b = blockIdx.y;
    int p = blockIdx.x * blockDim.x + t;
    if (p >= npix) return;
    const float* xb = x + (size_t)b * CCH * npix;
    float acc[COUT];
    #pragma unroll
    for (int o = 0; o < COUT; o++) acc[o] = bs[o];
    #pragma unroll
    for (int c = 0; c < CCH; c++) {
        float xv = xb[(size_t)c*npix + p];
        #pragma unroll
        for (int o = 0; o < COUT; o++) acc[o] = fmaf(xv, ws[o*CCH + c], acc[o]);
    }
    if (DST == 1) {           // channel-major
        float* ob = outg + (size_t)b * COUT * npix;
        #pragma unroll
        for (int o = 0; o < COUT; o++) {
            float v = acc[o];
            ob[(size_t)o*npix + p] = (v >= 0.f) ? v : a * v;
        }
    } else {                  // pixel-major [p][COUT]
        float* ob = outg + ((size_t)b * npix + p) * COUT;
        #pragma unroll
        for (int o = 0; o < COUT; o += 4) {
            float4 vv;
            vv.x = (acc[o+0] >= 0.f) ? acc[o+0] : a * acc[o+0];
            vv.y = (acc[o+1] >= 0.f) ? acc[o+1] : a * acc[o+1];
            vv.z = (acc[o+2] >= 0.f) ? acc[o+2] : a * acc[o+2];
            vv.w = (acc[o+3] >= 0.f) ? acc[o+3] : a * acc[o+3];
            *(float4*)(ob + o) = vv;
        }
    }
}

// ---------------- im2col 3x3 (same pad) for embed -> Rim ----------------
__global__ void im2col3k() {
    const int Cn = CCH, Ht = HSS, Wt = HSS;
    int idx = blockIdx.x * blockDim.x + threadIdx.x;
    int total = BB * Cn * Ht * Wt;
    if (idx >= total) return;
    int xq = idx % Wt; int tmp = idx / Wt;
    int yq = tmp % Ht; tmp /= Ht;
    int c  = tmp % Cn; int b = tmp / Cn;
    const float* s = g_embed + ((size_t)(b*Cn + c)) * Ht * Wt;
    float* d = g_Rim + ((size_t)b*Ht*Wt + (size_t)yq*Wt + xq) * (Cn*9) + c*9;
    #pragma unroll
    for (int i = 0; i < 3; i++) {
        int yy = yq + i - 1;
        #pragma unroll
        for (int j = 0; j < 3; j++) {
            int xx = xq + j - 1;
            float v = (yy >= 0 && yy < Ht && xx >= 0 && xx < Wt) ? s[yy*Wt + xx] : 0.f;
            d[i*3 + j] = v;
        }
    }
}

// ---------------- per-pixel channel energy + patch inv-norm ----------------
__global__ void n2_kernel() {
    int idx = blockIdx.x * blockDim.x + threadIdx.x;
    if (idx >= BB*LLN) return;
    const float* r = g_ref + (size_t)idx * CRR;
    float s = 0.f;
    #pragma unroll
    for (int c = 0; c < CRR; c += 4) {
        float4 v = *(const float4*)(r + c);
        s = fmaf(v.x, v.x, s); s = fmaf(v.y, v.y, s);
        s = fmaf(v.z, v.z, s); s = fmaf(v.w, v.w, s);
    }
    g_n2[idx] = s;
}

__global__ void invn_kernel() {
    int idx = blockIdx.x * blockDim.x + threadIdx.x;
    if (idx >= BB*LLN) return;
    int b = idx / LLN, l = idx % LLN;
    int ly = l / HSS, lx = l % HSS;
    const float* n2b = g_n2 + b*LLN;
    float s = 0.f;
    #pragma unroll
    for (int dy = -1; dy <= 1; dy++)
        #pragma unroll
        for (int dx = -1; dx <= 1; dx++) {
            int yy = ly + dy, xx = lx + dx;
            if (yy >= 0 && yy < HSS && xx >= 0 && xx < HSS)
                s += n2b[yy*HSS + xx];
        }
    g_invn[idx] = 1.f / fmaxf(sqrtf(s), 1e-4f);
}

// ---------------- Gram GEMM: D = match [M,32] * ref [N,32]^T ----------------
// M=9216, N=2304, K=32. 128x128 tile, 8x8 per thread.
__global__ void __launch_bounds__(256) gemmD_kernel() {
    const int M = HWP, N = LLN, K = CRR;
    int bz = blockIdx.z;
    const float* __restrict__ A  = g_match + (size_t)bz*M*K;
    const float* __restrict__ Bp = g_ref   + (size_t)bz*N*K;
    float* __restrict__ Dp = g_D + (size_t)bz*M*N;
    __shared__ float As[32][132];
    __shared__ float Bs[32][132];
    int t = threadIdx.x;
    int m0 = blockIdx.y * 128, n0 = blockIdx.x * 128;
    int lr = t >> 1, lc = (t & 1) * 16;
    int tx = t & 15, ty = t >> 4;
    #pragma unroll
    for (int q = 0; q < 4; q++) {
        float4 av = *(const float4*)(A  + (size_t)(m0+lr)*K + lc + q*4);
        As[lc+q*4+0][lr]=av.x; As[lc+q*4+1][lr]=av.y;
        As[lc+q*4+2][lr]=av.z; As[lc+q*4+3][lr]=av.w;
        float4 bv = *(const float4*)(Bp + (size_t)(n0+lr)*K + lc + q*4);
        Bs[lc+q*4+0][lr]=bv.x; Bs[lc+q*4+1][lr]=bv.y;
        Bs[lc+q*4+2][lr]=bv.z; Bs[lc+q*4+3][lr]=bv.w;
    }
    __syncthreads();
    float acc[8][8];
    #pragma unroll
    for (int i = 0; i < 8; i++)
        #pragma unroll
        for (int j = 0; j < 8; j++) acc[i][j] = 0.f;
    #pragma unroll 4
    for (int kk = 0; kk < 32; kk++) {
        float ar[8], br[8];
        #pragma unroll
        for (int i = 0; i < 8; i++) ar[i] = As[kk][ty*8 + i];
        #pragma unroll
        for (int j = 0; j < 8; j++) br[j] = Bs[kk][tx*8 + j];
        #pragma unroll
        for (int i = 0; i < 8; i++)
            #pragma unroll
            for (int j = 0; j < 8; j++) acc[i][j] = fmaf(ar[i], br[j], acc[i][j]);
    }
    #pragma unroll
    for (int i = 0; i < 8; i++) {
        float* dr = Dp + (size_t)(m0 + ty*8 + i)*N + n0 + tx*8;
        *(float4*)(dr)     = make_float4(acc[i][0], acc[i][1], acc[i][2], acc[i][3]);
        *(float4*)(dr + 4) = make_float4(acc[i][4], acc[i][5], acc[i][6], acc[i][7]);
    }
}

// ---------------- fused diagonal stencil + softmax ----------------
// logit[p,l] = invn[l] * sum_{d in 3x3} D[p+d, l+d]  (both-valid taps only),
// then softmax over l with SCALE=10, written to g_S.
__global__ void __launch_bounds__(256) logits_softmax_kernel() {
    int row = blockIdx.x;
    int b = row / HWP, p = row % HWP;
    int py = p / WWD, px = p % WWD;
    const float* __restrict__ Db = g_D + (size_t)b*HWP*LLN;
    const float* __restrict__ invn = g_invn + b*LLN;
    float* __restrict__ Sr = g_S + (size_t)row * LLN;

    const float* rp[9]; bool rv[9]; int co[9];
    #pragma unroll
    for (int dy = -1; dy <= 1; dy++)
        #pragma unroll
        for (int dx = -1; dx <= 1; dx++) {
            int k = (dy+1)*3 + (dx+1);
            int yy = py + dy, xx = px + dx;
            rv[k] = (yy >= 0 && yy < HH && xx >= 0 && xx < WWD);
            rp[k] = Db + (size_t)(yy*WWD + xx) * LLN;
            co[k] = dy*HSS + dx;
        }

    int t = threadIdx.x;
    float v[9]; float m = -1e30f;
    #pragma unroll
    for (int i = 0; i < 9; i++) {
        int l = i*256 + t;
        int ly = l / HSS, lx = l % HSS;
        float s = 0.f;
        #pragma unroll
        for (int dy = -1; dy <= 1; dy++)
            #pragma unroll
            for (int dx = -1; dx <= 1; dx++) {
                int k = (dy+1)*3 + (dx+1);
                int yy = ly + dy, xx = lx + dx;
                bool ok = rv[k] && (yy >= 0) && (yy < HSS) && (xx >= 0) && (xx < HSS);
                if (ok) s += rp[k][l + co[k]];
            }
        v[i] = 10.f * s * invn[l];
        m = fmaxf(m, v[i]);
    }
    __shared__ float red[256];
    red[t] = m; __syncthreads();
    #pragma unroll
    for (int s = 128; s > 0; s >>= 1) { if (t < s) red[t] = fmaxf(red[t], red[t+s]); __syncthreads(); }
    m = red[0];
    __syncthreads();
    float sum = 0.f;
    #pragma unroll
    for (int i = 0; i < 9; i++) { v[i] = __expf(v[i] - m); sum += v[i]; }
    red[t] = sum; __syncthreads();
    #pragma unroll
    for (int s = 128; s > 0; s >>= 1) { if (t < s) red[t] += red[t+s]; __syncthreads(); }
    float inv = 1.f / red[0];
    #pragma unroll
    for (int i = 0; i < 9; i++) Sr[i*256 + t] = v[i] * inv;
}

// ---------------- GEMM2 (tf32 tensor cores): P2 = S [M,K] * Rim [K,N] ----------------
// M=9216, K=2304, N=576. Block 128x64, 8 warps (4x2), warp tile 32x32,
// k-step 16, double-buffered smem. All dims divide exactly (no guards).
// Smem layouts (conflict-free fragment LDS):
//   As[s][m][k]: k-stride 20 words  -> frag bank = (20*gr + gc) % 32, all distinct
//   Bs[s][k][n]: n-stride 72 words  -> frag bank = (8*gc + gr) % 32, all distinct
__global__ void __launch_bounds__(256) gemm2_tf32_kernel() {
    const int N = NN2, K = LLN;
    int bz = blockIdx.z;
    const float* __restrict__ A  = g_S   + (size_t)bz*HWP*K;
    const float* __restrict__ Bp = g_Rim + (size_t)bz*K*N;
    float* __restrict__ Cp = g_P2 + (size_t)bz*HWP*N;

    __shared__ unsigned As[2][128][20];
    __shared__ unsigned Bs[2][16][72];

    int t = threadIdx.x;
    int m0 = blockIdx.y * 128, n0 = blockIdx.x * 64;
    int wid = t >> 5, lane = t & 31;
    int wr = wid & 3, wc = wid >> 2;      // warp grid 4 x 2
    int gr = lane >> 2, gc = lane & 3;

    // staging assignment
    int arow = t >> 2;            // 0..63  (and arow+64)
    int acol = (t & 3) * 4;       // 0,4,8,12
    int brow = t >> 4;            // 0..15
    int bcol = (t & 15) * 4;      // 0..60

    const float* aP0 = A  + (size_t)(m0 + arow)      * K + acol;
    const float* aP1 = A  + (size_t)(m0 + arow + 64) * K + acol;
    const float* bP  = Bp + (size_t)brow * N + n0 + bcol;

    float acc[2][4][4];
    #pragma unroll
    for (int mt = 0; mt < 2; mt++)
        #pragma unroll
        for (int nt = 0; nt < 4; nt++)
            #pragma unroll
            for (int q = 0; q < 4; q++) acc[mt][nt][q] = 0.f;

    float4 av0 = *(const float4*)(aP0);
    float4 av1 = *(const float4*)(aP1);
    float4 bv  = *(const float4*)(bP);

    // store stage 0
    {
        As[0][arow][acol+0]    = to_tf32(av0.x);
        As[0][arow][acol+1]    = to_tf32(av0.y);
        As[0][arow][acol+2]    = to_tf32(av0.z);
        As[0][arow][acol+3]    = to_tf32(av0.w);
        As[0][arow+64][acol+0] = to_tf32(av1.x);
        As[0][arow+64][acol+1] = to_tf32(av1.y);
        As[0][arow+64][acol+2] = to_tf32(av1.z);
        As[0][arow+64][acol+3] = to_tf32(av1.w);
        uint4 bq;
        bq.x = to_tf32(bv.x); bq.y = to_tf32(bv.y);
        bq.z = to_tf32(bv.z); bq.w = to_tf32(bv.w);
        *(uint4*)&Bs[0][brow][bcol] = bq;
    }
    __syncthreads();

    const int KT = K / 16;   // 144
    for (int kt = 0; kt < KT; kt++) {
        if (kt + 1 < KT) {
            av0 = *(const float4*)(aP0 + (kt+1)*16);
            av1 = *(const float4*)(aP1 + (kt+1)*16);
            bv  = *(const float4*)(bP + (size_t)(kt+1)*16*N);
        }
        int s = kt & 1;
        int mb0 = wr*32, nb0 = wc*32;
        #pragma unroll
        for (int kh = 0; kh < 2; kh++) {
            int kb = kh * 8;
            unsigned af[2][4];
            #pragma unroll
            for (int mt = 0; mt < 2; mt++) {
                int mb = mb0 + mt*16;
                af[mt][0] = As[s][mb + gr    ][kb + gc];
                af[mt][1] = As[s][mb + gr + 8][kb + gc];
                af[mt][2] = As[s][mb + gr    ][kb + gc + 4];
                af[mt][3] = As[s][mb + gr + 8][kb + gc + 4];
            }
            unsigned bf[4][2];
            #pragma unroll
            for (int nt = 0; nt < 4; nt++) {
                int nb = nb0 + nt*8;
                bf[nt][0] = Bs[s][kb + gc    ][nb + gr];
                bf[nt][1] = Bs[s][kb + gc + 4][nb + gr];
            }
            #pragma unroll
            for (int mt = 0; mt < 2; mt++)
                #pragma unroll
                for (int nt = 0; nt < 4; nt++) {
                    asm volatile(
                        "mma.sync.aligned.m16n8k8.row.col.f32.tf32.tf32.f32 "
                        "{%0,%1,%2,%3}, {%4,%5,%6,%7}, {%8,%9}, {%0,%1,%2,%3};"
                        : "+f"(acc[mt][nt][0]), "+f"(acc[mt][nt][1]),
                          "+f"(acc[mt][nt][2]), "+f"(acc[mt][nt][3])
                        : "r"(af[mt][0]), "r"(af[mt][1]), "r"(af[mt][2]), "r"(af[mt][3]),
                          "r"(bf[nt][0]), "r"(bf[nt][1]));
                }
        }
        if (kt + 1 < KT) {
            int s2 = (kt + 1) & 1;
            As[s2][arow][acol+0]    = to_tf32(av0.x);
            As[s2][arow][acol+1]    = to_tf32(av0.y);
            As[s2][arow][acol+2]    = to_tf32(av0.z);
            As[s2][arow][acol+3]    = to_tf32(av0.w);
            As[s2][arow+64][acol+0] = to_tf32(av1.x);
            As[s2][arow+64][acol+1] = to_tf32(av1.y);
            As[s2][arow+64][acol+2] = to_tf32(av1.z);
            As[s2][arow+64][acol+3] = to_tf32(av1.w);
            uint4 bq;
            bq.x = to_tf32(bv.x); bq.y = to_tf32(bv.y);
            bq.z = to_tf32(bv.z); bq.w = to_tf32(bv.w);
            *(uint4*)&Bs[s2][brow][bcol] = bq;
        }
        __syncthreads();
    }

    // epilogue
    #pragma unroll
    for (int mt = 0; mt < 2; mt++) {
        int row = m0 + wr*32 + mt*16 + gr;
        #pragma unroll
        for (int nt = 0; nt < 4; nt++) {
            int col = n0 + wc*32 + nt*8 + 2*gc;
            *(float2*)(Cp + (size_t)row*N + col) =
                make_float2(acc[mt][nt][0], acc[mt][nt][1]);
            *(float2*)(Cp + (size_t)(row+8)*N + col) =
                make_float2(acc[mt][nt][2], acc[mt][nt][3]);
        }
    }
}

// ---------------- stride-2 transpose-conv gather ----------------
__global__ void gather_kernel(float* __restrict__ out) {
    long idx = (long)blockIdx.x * blockDim.x + threadIdx.x;
    const long total = (long)BB * CCH * HO * HO;
    if (idx >= total) return;
    int X = (int)(idx % HO); long tmp = idx / HO;
    int Y = (int)(tmp % HO); tmp /= HO;
    int c = (int)(tmp % CCH); int b = (int)(tmp / CCH);
    const float* __restrict__ Pb = g_P2 + (size_t)b * HWP * NN2 + c*9;

    float s;
    if ((Y & 1) == 0 && (X & 1) == 0) {
        int p = (Y >> 1)*WWD + (X >> 1);
        s = Pb[(size_t)p*NN2 + 4];                       // kh=1,kw=1
    } else if ((Y & 1) == 0) {
        int p0 = (Y >> 1)*WWD + ((X-1) >> 1);
        int p1 = (Y >> 1)*WWD + ((X+1) >> 1);
        s = Pb[(size_t)p0*NN2 + 5] + Pb[(size_t)p1*NN2 + 3];   // kw=2 / kw=0
    } else if ((X & 1) == 0) {
        int p0 = ((Y-1) >> 1)*WWD + (X >> 1);
        int p1 = ((Y+1) >> 1)*WWD + (X >> 1);
        s = Pb[(size_t)p0*NN2 + 7] + Pb[(size_t)p1*NN2 + 1];   // kh=2 / kh=0
    } else {
        int ya = (Y-1) >> 1, yb = (Y+1) >> 1;
        int xa = (X-1) >> 1, xb = (X+1) >> 1;
        s = Pb[(size_t)(ya*WWD + xa)*NN2 + 8]
          + Pb[(size_t)(ya*WWD + xb)*NN2 + 6]
          + Pb[(size_t)(yb*WWD + xa)*NN2 + 2]
          + Pb[(size_t)(yb*WWD + xb)*NN2 + 0];
    }
    out[idx] = s * (1.f/6.f);
}

// ---------------- launch ----------------
extern "C" void kernel_launch(void* const* d_in, const int* in_sizes, int n_in,
                              void* d_out, int out_size) {
    const float* input = (const float*)d_in[0];
    const float* small = (const float*)d_in[1];
    const float* w1    = (const float*)d_in[2];
    const float* b1    = (const float*)d_in[3];
    const float* a1    = (const float*)d_in[4];
    const float* w2    = (const float*)d_in[5];
    const float* b2    = (const float*)d_in[6];
    const float* a2    = (const float*)d_in[7];
    const float* wa    = (const float*)d_in[8];
    const float* ba    = (const float*)d_in[9];
    const float* aa    = (const float*)d_in[10];
    float* out = (float*)d_out;

    conv1x1k<CRR, 0><<<dim3(HWP/256, BB), 256>>>(input, w1, b1, a1, HWP);
    conv1x1k<CCH, 1><<<dim3(LLN/256, BB), 256>>>(small, wa, ba, aa, LLN);
    conv1x1k<CRR, 2><<<dim3(LLN/256, BB), 256>>>(small, w2, b2, a2, LLN);

    im2col3k<<<(BB*CCH*LLN + 255)/256, 256>>>();
    n2_kernel<<<(BB*LLN + 255)/256, 256>>>();
    invn_kernel<<<(BB*LLN + 255)/256, 256>>>();

    gemmD_kernel<<<dim3(LLN/128, HWP/128, BB), 256>>>();
    logits_softmax_kernel<<<BB*HWP, 256>>>();
    gemm2_tf32_kernel<<<dim3(NN2/64, HWP/128, BB), 256>>>();

    gather_kernel<<<(int)(((long)BB*CCH*HO*HO + 255)/256), 256>>>(out);
}